// round 4
// baseline (speedup 1.0000x reference)
#include <cuda_runtime.h>

#define N_NODES 50000
#define N_EDGES 800000
#define IN_DIM 128
#define HID 64
#define N_LAYERS 3
#define CH 4   // edges processed per warp pass

// ---------------- scratch (no allocations allowed) ----------------
__device__ float g_h[N_NODES * HID];
__device__ float g_A[N_NODES * HID];   // A[dst] = h@(W1a-W1b) + b1
__device__ float g_Q[N_NODES * HID];   // Q[src] = h@W1b
__device__ int   g_counts[N_NODES];
__device__ int   g_offsets[N_NODES + 1];
__device__ int   g_cursor[N_NODES];
__device__ int   g_csr[N_EDGES];       // src per dst-sorted slot
__device__ int   g_is64;               // edge_index dtype flag

// ---------------- f32x2 helpers ----------------
__device__ __forceinline__ unsigned long long pk2(float x, float y) {
    unsigned long long r;
    asm("mov.b64 %0, {%1, %2};" : "=l"(r) : "f"(x), "f"(y));
    return r;
}
__device__ __forceinline__ float2 upk2(unsigned long long v) {
    float2 r;
    asm("mov.b64 {%0, %1}, %2;" : "=f"(r.x), "=f"(r.y) : "l"(v));
    return r;
}
__device__ __forceinline__ unsigned long long ffma2(unsigned long long a,
                                                    unsigned long long b,
                                                    unsigned long long c) {
#if __CUDA_ARCH__ >= 1000
    unsigned long long d;
    asm("fma.rn.f32x2 %0, %1, %2, %3;" : "=l"(d) : "l"(a), "l"(b), "l"(c));
    return d;
#else
    float2 fa = upk2(a), fb = upk2(b), fc = upk2(c);
    return pk2(fmaf(fa.x, fb.x, fc.x), fmaf(fa.y, fb.y, fc.y));
#endif
}

// ---------------- edge-index dtype detection ----------------
// int64 buffer with values in [0, 2^31): high (odd int32) words are all 0.
// int32 buffer: odd words are random edge ids (all-zero prob ~ 5e-38).
__global__ void k_detect(const int* __restrict__ ei32) {
    int z = 0;
#pragma unroll
    for (int i = 1; i < 16; i += 2) z |= ei32[i];
    g_is64 = (z == 0) ? 1 : 0;
}

__device__ __forceinline__ int edge_val(const int* __restrict__ ei32, int idx, int is64) {
    return is64 ? ei32[2 * idx] : ei32[idx];   // little-endian low word
}

// ---------------- CSR build ----------------
__global__ void k_zero() {
    int i = blockIdx.x * blockDim.x + threadIdx.x;
    if (i < N_NODES) g_counts[i] = 0;
}

__global__ void k_hist(const int* __restrict__ ei32) {
    int e = blockIdx.x * blockDim.x + threadIdx.x;
    if (e < N_EDGES) {
        int d = edge_val(ei32, N_EDGES + e, g_is64);   // row 1 = dst
        if ((unsigned)d < (unsigned)N_NODES) atomicAdd(&g_counts[d], 1);
    }
}

__global__ void k_scan() {
    __shared__ int part[1024];
    int tid = threadIdx.x;
    const int CHK = (N_NODES + 1023) / 1024;  // 49
    int base = tid * CHK;
    int s = 0;
    for (int i = 0; i < CHK; i++) {
        int idx = base + i;
        if (idx < N_NODES) s += g_counts[idx];
    }
    part[tid] = s;
    __syncthreads();
    for (int off = 1; off < 1024; off <<= 1) {
        int v = 0;
        if (tid >= off) v = part[tid - off];
        __syncthreads();
        if (tid >= off) part[tid] += v;
        __syncthreads();
    }
    int run = (tid == 0) ? 0 : part[tid - 1];
    for (int i = 0; i < CHK; i++) {
        int idx = base + i;
        if (idx < N_NODES) {
            g_offsets[idx] = run;
            g_cursor[idx] = run;
            run += g_counts[idx];
        }
    }
    if (tid == 1023) g_offsets[N_NODES] = run;
}

__global__ void k_scatter(const int* __restrict__ ei32) {
    int e = blockIdx.x * blockDim.x + threadIdx.x;
    if (e < N_EDGES) {
        int is64 = g_is64;
        int d = edge_val(ei32, N_EDGES + e, is64);
        int s = edge_val(ei32, e, is64);
        if ((unsigned)d < (unsigned)N_NODES && (unsigned)s < (unsigned)N_NODES) {
            int pos = atomicAdd(&g_cursor[d], 1);
            g_csr[pos] = s;
        }
    }
}

// ---------------- input projection: h = x @ Wp + bp ----------------
__global__ void __launch_bounds__(256) k_proj(const float* __restrict__ x,
                                              const float* __restrict__ Wp,
                                              const float* __restrict__ bp) {
    __shared__ float Ws[IN_DIM * HID];       // 32 KB
    __shared__ float xs[8][IN_DIM];          // 4 KB
    int tid = threadIdx.x;
    for (int i = tid; i < IN_DIM * HID; i += 256) Ws[i] = Wp[i];
    int w = tid >> 5, l = tid & 31;
    int n = blockIdx.x * 8 + w;
    if (n < N_NODES) {
        float4 v = ((const float4*)(x + (long)n * IN_DIM))[l];
        ((float4*)xs[w])[l] = v;
    }
    __syncthreads();
    if (n >= N_NODES) return;
    float2 acc = *(const float2*)(bp + 2 * l);
#pragma unroll 8
    for (int k = 0; k < IN_DIM; k++) {
        float xk = xs[w][k];
        float2 wv = *(const float2*)(Ws + k * HID + 2 * l);
        acc.x = fmaf(xk, wv.x, acc.x);
        acc.y = fmaf(xk, wv.y, acc.y);
    }
    *(float2*)(g_h + (long)n * HID + 2 * l) = acc;
}

// ---------------- per-layer node GEMMs: A = h@(W1a-W1b)+b1 ; Q = h@W1b ----------------
__global__ void __launch_bounds__(256) k_AQ(const float* __restrict__ W1,
                                            const float* __restrict__ b1) {
    __shared__ float Ws[2 * HID * HID];      // 32 KB
    __shared__ float hs[8][HID];             // 2 KB
    int tid = threadIdx.x;
    for (int i = tid; i < 2 * HID * HID; i += 256) Ws[i] = W1[i];
    int w = tid >> 5, l = tid & 31;
    int n = blockIdx.x * 8 + w;
    if (n < N_NODES) {
        ((float2*)hs[w])[l] = *(const float2*)(g_h + (long)n * HID + 2 * l);
    }
    __syncthreads();
    if (n >= N_NODES) return;
    float2 aA = *(const float2*)(b1 + 2 * l);
    float2 aQ = make_float2(0.f, 0.f);
#pragma unroll 8
    for (int k = 0; k < HID; k++) {
        float hk = hs[w][k];
        float2 wa = *(const float2*)(Ws + k * HID + 2 * l);
        float2 wb = *(const float2*)(Ws + (HID + k) * HID + 2 * l);
        aA.x = fmaf(hk, wa.x - wb.x, aA.x);
        aA.y = fmaf(hk, wa.y - wb.y, aA.y);
        aQ.x = fmaf(hk, wb.x, aQ.x);
        aQ.y = fmaf(hk, wb.y, aQ.y);
    }
    *(float2*)(g_A + (long)n * HID + 2 * l) = aA;
    *(float2*)(g_Q + (long)n * HID + 2 * l) = aQ;
}

// ---------------- edge phase: per-node max over relu(A[dst]+Q[src]) @ W2 ----------------
// warp per dst node; CH edges per pass; FFMA2 inner GEMM with SMEM-resident W2
__global__ void __launch_bounds__(256) k_edge(const float* __restrict__ W2,
                                              const float* __restrict__ b2) {
    // W2q[k2*32 + l] = {pk(W2[2k2][2l],W2[2k2][2l+1]), pk(W2[2k2+1][2l],W2[2k2+1][2l+1])}
    __shared__ ulonglong2 W2q[32 * 32];      // 16 KB
    __shared__ ulonglong2 us[8][CH][32];     // 16 KB: u duplicated pairs per edge
    int tid = threadIdx.x;
    for (int i = tid; i < 1024; i += 256) {
        int k2 = i >> 5, l = i & 31;
        const float* p0 = W2 + (2 * k2) * HID + 2 * l;
        const float* p1 = W2 + (2 * k2 + 1) * HID + 2 * l;
        ulonglong2 v;
        v.x = pk2(p0[0], p0[1]);
        v.y = pk2(p1[0], p1[1]);
        W2q[i] = v;
    }
    int w = tid >> 5, l = tid & 31;
    int n = blockIdx.x * 8 + w;
    __syncthreads();
    if (n >= N_NODES) return;

    int start = g_offsets[n];
    int deg = g_offsets[n + 1] - start;
    if (deg == 0) return;  // agg=0, relu(0)=0, +residual -> h unchanged

    float2 a = *(const float2*)(g_A + (long)n * HID + 2 * l);
    float zmx0 = -INFINITY, zmx1 = -INFINITY;

    for (int c0 = 0; c0 < deg; c0 += CH) {
#pragma unroll
        for (int e = 0; e < CH; e++) {
            if (c0 + e < deg) {
                int s = g_csr[start + c0 + e];
                float2 b = *(const float2*)(g_Q + (long)s * HID + 2 * l);
                float u0 = fmaxf(a.x + b.x, 0.f);
                float u1 = fmaxf(a.y + b.y, 0.f);
                ulonglong2 v;
                v.x = pk2(u0, u0);
                v.y = pk2(u1, u1);
                us[w][e][l] = v;
            }
        }
        __syncwarp();
        unsigned long long z[CH];
#pragma unroll
        for (int e = 0; e < CH; e++) z[e] = 0ull;  // (0.f, 0.f)
#pragma unroll 8
        for (int k2 = 0; k2 < 32; k2++) {
            ulonglong2 wv = W2q[k2 * 32 + l];
#pragma unroll
            for (int e = 0; e < CH; e++) {
                ulonglong2 u = us[w][e][k2];
                z[e] = ffma2(u.x, wv.x, z[e]);
                z[e] = ffma2(u.y, wv.y, z[e]);
            }
        }
        __syncwarp();
#pragma unroll
        for (int e = 0; e < CH; e++) {
            if (c0 + e < deg) {
                float2 zf = upk2(z[e]);
                zmx0 = fmaxf(zmx0, zf.x);
                zmx1 = fmaxf(zmx1, zf.y);
            }
        }
    }

    float2 hold = *(const float2*)(g_h + (long)n * HID + 2 * l);
    float2 b2v = *(const float2*)(b2 + 2 * l);
    float2 r;
    r.x = fmaxf(zmx0 + b2v.x, 0.f) + hold.x;
    r.y = fmaxf(zmx1 + b2v.y, 0.f) + hold.y;
    *(float2*)(g_h + (long)n * HID + 2 * l) = r;
}

// ---------------- output: out = h @ Wo + bo ----------------
__global__ void __launch_bounds__(256) k_out(const float* __restrict__ Wo,
                                             const float* __restrict__ bo,
                                             float* __restrict__ out) {
    int w = threadIdx.x >> 5, l = threadIdx.x & 31;
    int n = blockIdx.x * 8 + w;
    if (n >= N_NODES) return;
    float2 h2 = *(const float2*)(g_h + (long)n * HID + 2 * l);
    float2 wo = *(const float2*)(Wo + 2 * l);
    float s = fmaf(h2.x, wo.x, h2.y * wo.y);
#pragma unroll
    for (int o = 16; o; o >>= 1) s += __shfl_xor_sync(0xffffffffu, s, o);
    if (l == 0) out[n] = s + bo[0];
}

// ---------------- launch ----------------
extern "C" void kernel_launch(void* const* d_in, const int* in_sizes, int n_in,
                              void* d_out, int out_size) {
    const float* x  = (const float*)d_in[0];
    const int*   ei = (const int*)d_in[1];   // int32 view; dtype detected at runtime
    const float* Wp = (const float*)d_in[2];
    const float* bp = (const float*)d_in[3];
    const float* W1 = (const float*)d_in[4];
    const float* b1 = (const float*)d_in[5];
    const float* W2 = (const float*)d_in[6];
    const float* b2 = (const float*)d_in[7];
    const float* Wo = (const float*)d_in[8];
    const float* bo = (const float*)d_in[9];
    float* out = (float*)d_out;

    k_detect<<<1, 1>>>(ei);
    k_zero<<<(N_NODES + 255) / 256, 256>>>();
    k_hist<<<(N_EDGES + 255) / 256, 256>>>(ei);
    k_scan<<<1, 1024>>>();
    k_scatter<<<(N_EDGES + 255) / 256, 256>>>(ei);

    const int NB = (N_NODES + 7) / 8;  // 6250 blocks, warp per node
    k_proj<<<NB, 256>>>(x, Wp, bp);
    for (int l = 0; l < N_LAYERS; l++) {
        k_AQ<<<NB, 256>>>(W1 + (long)l * 2 * HID * HID, b1 + (long)l * HID);
        k_edge<<<NB, 256>>>(W2 + (long)l * HID * HID, b2 + (long)l * HID);
    }
    k_out<<<NB, 256>>>(Wo, bo, out);
}

// round 6
// speedup vs baseline: 1.0235x; 1.0235x over previous
#include <cuda_runtime.h>

#define N_NODES 50000
#define N_EDGES 800000
#define IN_DIM 128
#define HID 64
#define N_LAYERS 3
#define CH 4            // edges per warp pass
#define SCB 512
#define NSB ((N_NODES + SCB - 1) / SCB)   // 98 scan blocks

// ---------------- scratch (no allocations allowed) ----------------
__device__ float g_h[N_NODES * HID];
__device__ float g_A[N_NODES * HID];   // A[dst] = h@(W1a-W1b) + b1
__device__ float g_Q[N_NODES * HID];   // Q[src] = h@W1b
__device__ int   g_counts[N_NODES];
__device__ int   g_offsets[N_NODES + 1];
__device__ int   g_cursor[N_NODES];
__device__ int   g_csr[N_EDGES];
__device__ int   g_bsum[128];
__device__ int   g_bbase[128];
__device__ int   g_is64;

// ---------------- f32x2 helpers ----------------
__device__ __forceinline__ unsigned long long pk2(float x, float y) {
    unsigned long long r;
    asm("mov.b64 %0, {%1, %2};" : "=l"(r) : "f"(x), "f"(y));
    return r;
}
__device__ __forceinline__ float2 upk2(unsigned long long v) {
    float2 r;
    asm("mov.b64 {%0, %1}, %2;" : "=f"(r.x), "=f"(r.y) : "l"(v));
    return r;
}
__device__ __forceinline__ unsigned long long ffma2(unsigned long long a,
                                                    unsigned long long b,
                                                    unsigned long long c) {
#if __CUDA_ARCH__ >= 1000
    unsigned long long d;
    asm("fma.rn.f32x2 %0, %1, %2, %3;" : "=l"(d) : "l"(a), "l"(b), "l"(c));
    return d;
#else
    float2 fa = upk2(a), fb = upk2(b), fc = upk2(c);
    return pk2(fmaf(fa.x, fb.x, fc.x), fmaf(fa.y, fb.y, fc.y));
#endif
}

// ---------------- zero + dtype detect (merged) ----------------
// int64 edge_index with values < 2^31 has all-zero high (odd int32) words.
__global__ void k_zero(const int* __restrict__ ei32) {
    int i = blockIdx.x * blockDim.x + threadIdx.x;
    if (i < N_NODES) g_counts[i] = 0;
    if (blockIdx.x == 0 && threadIdx.x == 0) {
        int z = 0;
#pragma unroll
        for (int j = 1; j < 16; j += 2) z |= ei32[j];
        g_is64 = (z == 0) ? 1 : 0;
    }
}

__device__ __forceinline__ int edge_val(const int* __restrict__ ei32, int idx, int is64) {
    return is64 ? ei32[2 * idx] : ei32[idx];
}

__global__ void k_hist(const int* __restrict__ ei32) {
    int e = blockIdx.x * blockDim.x + threadIdx.x;
    if (e < N_EDGES) {
        int d = edge_val(ei32, N_EDGES + e, g_is64);
        if ((unsigned)d < (unsigned)N_NODES) atomicAdd(&g_counts[d], 1);
    }
}

// ---------------- 3-pass scan ----------------
__device__ __forceinline__ int warp_incl_scan(int v, int lane) {
#pragma unroll
    for (int o = 1; o < 32; o <<= 1) {
        int t = __shfl_up_sync(0xffffffffu, v, o);
        if (lane >= o) v += t;
    }
    return v;
}

__global__ void __launch_bounds__(SCB) k_scan1() {   // per-block reduce
    __shared__ int ws[SCB / 32];
    int tid = threadIdx.x, lane = tid & 31, wid = tid >> 5;
    int i = blockIdx.x * SCB + tid;
    int v = (i < N_NODES) ? g_counts[i] : 0;
#pragma unroll
    for (int o = 16; o; o >>= 1) v += __shfl_xor_sync(0xffffffffu, v, o);
    if (lane == 0) ws[wid] = v;
    __syncthreads();
    if (wid == 0) {
        int s = (lane < SCB / 32) ? ws[lane] : 0;
#pragma unroll
        for (int o = 16; o; o >>= 1) s += __shfl_xor_sync(0xffffffffu, s, o);
        if (lane == 0) g_bsum[blockIdx.x] = s;
    }
}

__global__ void __launch_bounds__(128) k_scan2() {   // scan 98 block sums
    __shared__ int wsum[4];
    int tid = threadIdx.x, lane = tid & 31, wid = tid >> 5;
    int c = (tid < NSB) ? g_bsum[tid] : 0;
    int v = warp_incl_scan(c, lane);
    if (lane == 31) wsum[wid] = v;
    __syncthreads();
    int base = 0;
    for (int j = 0; j < wid; j++) base += wsum[j];
    v += base;
    if (tid < NSB) g_bbase[tid] = v - c;          // exclusive base per block
    if (tid == NSB - 1) g_offsets[N_NODES] = v;   // total
}

__global__ void __launch_bounds__(SCB) k_scan3() {   // per-block exclusive scan + base
    __shared__ int wsum[SCB / 32];
    int tid = threadIdx.x, lane = tid & 31, wid = tid >> 5;
    int i = blockIdx.x * SCB + tid;
    int c = (i < N_NODES) ? g_counts[i] : 0;
    int v = warp_incl_scan(c, lane);
    if (lane == 31) wsum[wid] = v;
    __syncthreads();
    int base = g_bbase[blockIdx.x];
    for (int j = 0; j < wid; j++) base += wsum[j];
    int excl = base + v - c;
    if (i < N_NODES) {
        g_offsets[i] = excl;
        g_cursor[i]  = excl;
    }
}

__global__ void k_scatter(const int* __restrict__ ei32) {
    int e = blockIdx.x * blockDim.x + threadIdx.x;
    if (e < N_EDGES) {
        int is64 = g_is64;
        int d = edge_val(ei32, N_EDGES + e, is64);
        int s = edge_val(ei32, e, is64);
        if ((unsigned)d < (unsigned)N_NODES && (unsigned)s < (unsigned)N_NODES) {
            int pos = atomicAdd(&g_cursor[d], 1);
            g_csr[pos] = s;
        }
    }
}

// ---------------- input projection: h = x @ Wp + bp (32 nodes/block) ----------------
__global__ void __launch_bounds__(256) k_proj(const float* __restrict__ x,
                                              const float* __restrict__ Wp,
                                              const float* __restrict__ bp) {
    __shared__ float Ws[IN_DIM * HID];   // 32 KB
    __shared__ float xs[32][IN_DIM];     // 16 KB
    int tid = threadIdx.x;
    for (int i = tid; i < IN_DIM * HID; i += 256) Ws[i] = Wp[i];
    int w = tid >> 5, l = tid & 31;
#pragma unroll
    for (int sub = 0; sub < 4; sub++) {
        int m = w * 4 + sub;
        int n = blockIdx.x * 32 + m;
        if (n < N_NODES)
            ((float4*)xs[m])[l] = ((const float4*)(x + (long)n * IN_DIM))[l];
    }
    __syncthreads();
    float2 bv = *(const float2*)(bp + 2 * l);
#pragma unroll
    for (int sub = 0; sub < 4; sub++) {
        int m = w * 4 + sub;
        int n = blockIdx.x * 32 + m;
        if (n >= N_NODES) continue;
        float2 acc = bv;
#pragma unroll 8
        for (int k = 0; k < IN_DIM; k++) {
            float xk = xs[m][k];
            float2 wv = *(const float2*)(Ws + k * HID + 2 * l);
            acc.x = fmaf(xk, wv.x, acc.x);
            acc.y = fmaf(xk, wv.y, acc.y);
        }
        *(float2*)(g_h + (long)n * HID + 2 * l) = acc;
    }
}

// ---------------- node GEMMs: A = h@(W1a-W1b)+b1 ; Q = h@W1b (32 nodes/block) --------
__global__ void __launch_bounds__(256) k_AQ(const float* __restrict__ W1,
                                            const float* __restrict__ b1) {
    __shared__ float Ws[2 * HID * HID];  // 32 KB
    __shared__ float hs[32][HID];        // 8 KB
    int tid = threadIdx.x;
    for (int i = tid; i < 2 * HID * HID; i += 256) Ws[i] = W1[i];
    int w = tid >> 5, l = tid & 31;
#pragma unroll
    for (int sub = 0; sub < 4; sub++) {
        int m = w * 4 + sub;
        int n = blockIdx.x * 32 + m;
        if (n < N_NODES)
            ((float2*)hs[m])[l] = *(const float2*)(g_h + (long)n * HID + 2 * l);
    }
    __syncthreads();
    float2 bv = *(const float2*)(b1 + 2 * l);
#pragma unroll
    for (int sub = 0; sub < 4; sub++) {
        int m = w * 4 + sub;
        int n = blockIdx.x * 32 + m;
        if (n >= N_NODES) continue;
        float2 aA = bv;
        float2 aQ = make_float2(0.f, 0.f);
#pragma unroll 8
        for (int k = 0; k < HID; k++) {
            float hk = hs[m][k];
            float2 wa = *(const float2*)(Ws + k * HID + 2 * l);
            float2 wb = *(const float2*)(Ws + (HID + k) * HID + 2 * l);
            aA.x = fmaf(hk, wa.x - wb.x, aA.x);
            aA.y = fmaf(hk, wa.y - wb.y, aA.y);
            aQ.x = fmaf(hk, wb.x, aQ.x);
            aQ.y = fmaf(hk, wb.y, aQ.y);
        }
        *(float2*)(g_A + (long)n * HID + 2 * l) = aA;
        *(float2*)(g_Q + (long)n * HID + 2 * l) = aQ;
    }
}

// ---------------- edge phase (32 nodes/block); last layer fuses output -------------
__global__ void __launch_bounds__(256) k_edge(const float* __restrict__ W2,
                                              const float* __restrict__ b2,
                                              const float* __restrict__ Wo,
                                              const float* __restrict__ bo,
                                              float* __restrict__ out,
                                              int last) {
    __shared__ ulonglong2 W2q[32 * 32];      // 16 KB packed W2 k-pairs
    __shared__ ulonglong2 us[8][CH][32];     // 16 KB staged u (duplicated pairs)
    int tid = threadIdx.x;
    for (int i = tid; i < 1024; i += 256) {
        int k2 = i >> 5, lc = i & 31;
        const float* p0 = W2 + (2 * k2) * HID + 2 * lc;
        const float* p1 = W2 + (2 * k2 + 1) * HID + 2 * lc;
        ulonglong2 v;
        v.x = pk2(p0[0], p0[1]);
        v.y = pk2(p1[0], p1[1]);
        W2q[i] = v;
    }
    int w = tid >> 5, l = tid & 31;
    float2 b2v = *(const float2*)(b2 + 2 * l);
    float2 wo  = *(const float2*)(Wo + 2 * l);
    float  bov = bo[0];
    __syncthreads();

#pragma unroll
    for (int sub = 0; sub < 4; sub++) {
        int n = blockIdx.x * 32 + w * 4 + sub;
        if (n >= N_NODES) continue;

        int start = g_offsets[n];
        int deg = g_offsets[n + 1] - start;
        if (deg == 0 && !last) continue;   // h unchanged

        float2 hold = *(const float2*)(g_h + (long)n * HID + 2 * l);
        float2 r = hold;

        if (deg > 0) {
            float2 a = *(const float2*)(g_A + (long)n * HID + 2 * l);
            float zmx0 = -INFINITY, zmx1 = -INFINITY;

            for (int c0 = 0; c0 < deg; c0 += CH) {
                int sidx = (l < CH && c0 + l < deg) ? g_csr[start + c0 + l] : 0;
#pragma unroll
                for (int e = 0; e < CH; e++) {
                    if (c0 + e < deg) {
                        int s = __shfl_sync(0xffffffffu, sidx, e);
                        float2 b = *(const float2*)(g_Q + (long)s * HID + 2 * l);
                        float u0 = fmaxf(a.x + b.x, 0.f);
                        float u1 = fmaxf(a.y + b.y, 0.f);
                        ulonglong2 v;
                        v.x = pk2(u0, u0);
                        v.y = pk2(u1, u1);
                        us[w][e][l] = v;
                    }
                }
                __syncwarp();
                unsigned long long z[CH];
#pragma unroll
                for (int e = 0; e < CH; e++) z[e] = 0ull;
#pragma unroll 8
                for (int k2 = 0; k2 < 32; k2++) {
                    ulonglong2 wv = W2q[k2 * 32 + l];
#pragma unroll
                    for (int e = 0; e < CH; e++) {
                        ulonglong2 u = us[w][e][k2];
                        z[e] = ffma2(u.x, wv.x, z[e]);
                        z[e] = ffma2(u.y, wv.y, z[e]);
                    }
                }
                __syncwarp();
#pragma unroll
                for (int e = 0; e < CH; e++) {
                    if (c0 + e < deg) {
                        float2 zf = upk2(z[e]);
                        zmx0 = fmaxf(zmx0, zf.x);
                        zmx1 = fmaxf(zmx1, zf.y);
                    }
                }
            }
            r.x = fmaxf(zmx0 + b2v.x, 0.f) + hold.x;
            r.y = fmaxf(zmx1 + b2v.y, 0.f) + hold.y;
        }

        if (last) {
            // out[n] = sum(h_new * Wo) + bo
            float s = fmaf(r.x, wo.x, r.y * wo.y);
#pragma unroll
            for (int o = 16; o; o >>= 1) s += __shfl_xor_sync(0xffffffffu, s, o);
            if (l == 0) out[n] = s + bov;
        } else {
            *(float2*)(g_h + (long)n * HID + 2 * l) = r;
        }
    }
}

// ---------------- launch ----------------
extern "C" void kernel_launch(void* const* d_in, const int* in_sizes, int n_in,
                              void* d_out, int out_size) {
    const float* x  = (const float*)d_in[0];
    const int*   ei = (const int*)d_in[1];   // dtype detected at runtime
    const float* Wp = (const float*)d_in[2];
    const float* bp = (const float*)d_in[3];
    const float* W1 = (const float*)d_in[4];
    const float* b1 = (const float*)d_in[5];
    const float* W2 = (const float*)d_in[6];
    const float* b2 = (const float*)d_in[7];
    const float* Wo = (const float*)d_in[8];
    const float* bo = (const float*)d_in[9];
    float* out = (float*)d_out;

    k_zero<<<(N_NODES + 255) / 256, 256>>>(ei);
    k_hist<<<(N_EDGES + 255) / 256, 256>>>(ei);
    k_scan1<<<NSB, SCB>>>();
    k_scan2<<<1, 128>>>();
    k_scan3<<<NSB, SCB>>>();
    k_scatter<<<(N_EDGES + 255) / 256, 256>>>(ei);

    const int NB = (N_NODES + 31) / 32;   // 1563 blocks, 4 nodes per warp
    k_proj<<<NB, 256>>>(x, Wp, bp);
    for (int l = 0; l < N_LAYERS; l++) {
        k_AQ<<<NB, 256>>>(W1 + (long)l * 2 * HID * HID, b1 + (long)l * HID);
        k_edge<<<NB, 256>>>(W2 + (long)l * HID * HID, b2 + (long)l * HID,
                            Wo, bo, out, l == N_LAYERS - 1);
    }
}

// round 7
// speedup vs baseline: 1.2506x; 1.2219x over previous
#include <cuda_runtime.h>

#define N_NODES 50000
#define N_EDGES 800000
#define IN_DIM 128
#define HID 64
#define N_LAYERS 3
#define CH 8            // edges per warp pass
#define SCB 512
#define NSB ((N_NODES + SCB - 1) / SCB)   // 98 scan blocks

// ---------------- scratch (no allocations allowed) ----------------
__device__ float g_h[N_NODES * HID];
__device__ float g_A[N_NODES * HID];   // A[dst] = h@W1a - h@W1b + b1
__device__ float g_Q[N_NODES * HID];   // Q[src] = h@W1b
__device__ int   g_counts[N_NODES];
__device__ int   g_offsets[N_NODES + 1];
__device__ int   g_cursor[N_NODES];
__device__ int   g_csr[N_EDGES];
__device__ int   g_bsum[128];
__device__ int   g_bbase[128];
__device__ int   g_is64;

// ---------------- f32x2 helpers ----------------
__device__ __forceinline__ unsigned long long pk2(float x, float y) {
    unsigned long long r;
    asm("mov.b64 %0, {%1, %2};" : "=l"(r) : "f"(x), "f"(y));
    return r;
}
__device__ __forceinline__ unsigned long long pkdup(float x) {
    unsigned long long r;
    asm("mov.b64 %0, {%1, %1};" : "=l"(r) : "f"(x));
    return r;
}
__device__ __forceinline__ float2 upk2(unsigned long long v) {
    float2 r;
    asm("mov.b64 {%0, %1}, %2;" : "=f"(r.x), "=f"(r.y) : "l"(v));
    return r;
}
__device__ __forceinline__ unsigned long long ffma2(unsigned long long a,
                                                    unsigned long long b,
                                                    unsigned long long c) {
    unsigned long long d;
    asm("fma.rn.f32x2 %0, %1, %2, %3;" : "=l"(d) : "l"(a), "l"(b), "l"(c));
    return d;
}

// ---------------- zero + dtype detect ----------------
__global__ void k_zero(const int* __restrict__ ei32) {
    int i = blockIdx.x * blockDim.x + threadIdx.x;
    if (i < N_NODES) g_counts[i] = 0;
    if (blockIdx.x == 0 && threadIdx.x == 0) {
        int z = 0;
#pragma unroll
        for (int j = 1; j < 16; j += 2) z |= ei32[j];
        g_is64 = (z == 0) ? 1 : 0;
    }
}

__device__ __forceinline__ int edge_val(const int* __restrict__ ei32, int idx, int is64) {
    return is64 ? ei32[2 * idx] : ei32[idx];
}

__global__ void k_hist(const int* __restrict__ ei32) {
    int e = blockIdx.x * blockDim.x + threadIdx.x;
    if (e < N_EDGES) {
        int d = edge_val(ei32, N_EDGES + e, g_is64);
        if ((unsigned)d < (unsigned)N_NODES) atomicAdd(&g_counts[d], 1);
    }
}

// ---------------- 3-pass scan ----------------
__device__ __forceinline__ int warp_incl_scan(int v, int lane) {
#pragma unroll
    for (int o = 1; o < 32; o <<= 1) {
        int t = __shfl_up_sync(0xffffffffu, v, o);
        if (lane >= o) v += t;
    }
    return v;
}

__global__ void __launch_bounds__(SCB) k_scan1() {
    __shared__ int ws[SCB / 32];
    int tid = threadIdx.x, lane = tid & 31, wid = tid >> 5;
    int i = blockIdx.x * SCB + tid;
    int v = (i < N_NODES) ? g_counts[i] : 0;
#pragma unroll
    for (int o = 16; o; o >>= 1) v += __shfl_xor_sync(0xffffffffu, v, o);
    if (lane == 0) ws[wid] = v;
    __syncthreads();
    if (wid == 0) {
        int s = (lane < SCB / 32) ? ws[lane] : 0;
#pragma unroll
        for (int o = 16; o; o >>= 1) s += __shfl_xor_sync(0xffffffffu, s, o);
        if (lane == 0) g_bsum[blockIdx.x] = s;
    }
}

__global__ void __launch_bounds__(128) k_scan2() {
    __shared__ int wsum[4];
    int tid = threadIdx.x, lane = tid & 31, wid = tid >> 5;
    int c = (tid < NSB) ? g_bsum[tid] : 0;
    int v = warp_incl_scan(c, lane);
    if (lane == 31) wsum[wid] = v;
    __syncthreads();
    int base = 0;
    for (int j = 0; j < wid; j++) base += wsum[j];
    v += base;
    if (tid < NSB) g_bbase[tid] = v - c;
    if (tid == NSB - 1) g_offsets[N_NODES] = v;
}

__global__ void __launch_bounds__(SCB) k_scan3() {
    __shared__ int wsum[SCB / 32];
    int tid = threadIdx.x, lane = tid & 31, wid = tid >> 5;
    int i = blockIdx.x * SCB + tid;
    int c = (i < N_NODES) ? g_counts[i] : 0;
    int v = warp_incl_scan(c, lane);
    if (lane == 31) wsum[wid] = v;
    __syncthreads();
    int base = g_bbase[blockIdx.x];
    for (int j = 0; j < wid; j++) base += wsum[j];
    int excl = base + v - c;
    if (i < N_NODES) {
        g_offsets[i] = excl;
        g_cursor[i]  = excl;
    }
}

__global__ void k_scatter(const int* __restrict__ ei32) {
    int e = blockIdx.x * blockDim.x + threadIdx.x;
    if (e < N_EDGES) {
        int is64 = g_is64;
        int d = edge_val(ei32, N_EDGES + e, is64);
        int s = edge_val(ei32, e, is64);
        if ((unsigned)d < (unsigned)N_NODES && (unsigned)s < (unsigned)N_NODES) {
            int pos = atomicAdd(&g_cursor[d], 1);
            g_csr[pos] = s;
        }
    }
}

// ---------------- input projection: h = x @ Wp + bp ----------------
// 32 nodes/block; k-outer loop: weight pair loaded once per k for 4 nodes.
__global__ void __launch_bounds__(256) k_proj(const float* __restrict__ x,
                                              const float* __restrict__ Wp,
                                              const float* __restrict__ bp) {
    __shared__ unsigned long long Wsp[IN_DIM * 32];  // 32 KB packed pairs
    __shared__ float xs[32][IN_DIM];                 // 16 KB
    int tid = threadIdx.x;
    for (int i = tid; i < IN_DIM * 32; i += 256) {
        int k = i >> 5, lc = i & 31;
        Wsp[i] = pk2(Wp[k * HID + 2 * lc], Wp[k * HID + 2 * lc + 1]);
    }
    int w = tid >> 5, l = tid & 31;
    int m0 = w * 4;
#pragma unroll
    for (int sub = 0; sub < 4; sub++) {
        int n = blockIdx.x * 32 + m0 + sub;
        if (n < N_NODES)
            ((float4*)xs[m0 + sub])[l] = ((const float4*)(x + (long)n * IN_DIM))[l];
    }
    __syncthreads();
    unsigned long long bv = pk2(bp[2 * l], bp[2 * l + 1]);
    unsigned long long acc[4] = {bv, bv, bv, bv};
#pragma unroll 4
    for (int k = 0; k < IN_DIM; k++) {
        unsigned long long wv = Wsp[k * 32 + l];
#pragma unroll
        for (int sub = 0; sub < 4; sub++) {
            unsigned long long xk2 = pkdup(xs[m0 + sub][k]);
            acc[sub] = ffma2(xk2, wv, acc[sub]);
        }
    }
#pragma unroll
    for (int sub = 0; sub < 4; sub++) {
        int n = blockIdx.x * 32 + m0 + sub;
        if (n < N_NODES)
            *(float2*)(g_h + (long)n * HID + 2 * l) = upk2(acc[sub]);
    }
}

// ---------------- node GEMMs: A = h@W1a - h@W1b + b1 ; Q = h@W1b ----------------
__global__ void __launch_bounds__(256) k_AQ(const float* __restrict__ W1,
                                            const float* __restrict__ b1) {
    __shared__ unsigned long long Wsa[HID * 32];  // 16 KB
    __shared__ unsigned long long Wsb[HID * 32];  // 16 KB
    __shared__ float hs[32][HID];                 // 8 KB
    int tid = threadIdx.x;
    for (int i = tid; i < HID * 32; i += 256) {
        int k = i >> 5, lc = i & 31;
        Wsa[i] = pk2(W1[k * HID + 2 * lc], W1[k * HID + 2 * lc + 1]);
        Wsb[i] = pk2(W1[(HID + k) * HID + 2 * lc], W1[(HID + k) * HID + 2 * lc + 1]);
    }
    int w = tid >> 5, l = tid & 31;
    int m0 = w * 4;
#pragma unroll
    for (int sub = 0; sub < 4; sub++) {
        int n = blockIdx.x * 32 + m0 + sub;
        if (n < N_NODES)
            ((float2*)hs[m0 + sub])[l] = *(const float2*)(g_h + (long)n * HID + 2 * l);
    }
    __syncthreads();
    unsigned long long accA[4] = {0ull, 0ull, 0ull, 0ull};
    unsigned long long accQ[4] = {0ull, 0ull, 0ull, 0ull};
#pragma unroll 4
    for (int k = 0; k < HID; k++) {
        unsigned long long wa = Wsa[k * 32 + l];
        unsigned long long wb = Wsb[k * 32 + l];
#pragma unroll
        for (int sub = 0; sub < 4; sub++) {
            unsigned long long hk2 = pkdup(hs[m0 + sub][k]);
            accA[sub] = ffma2(hk2, wa, accA[sub]);
            accQ[sub] = ffma2(hk2, wb, accQ[sub]);
        }
    }
    float2 bv = *(const float2*)(b1 + 2 * l);
#pragma unroll
    for (int sub = 0; sub < 4; sub++) {
        int n = blockIdx.x * 32 + m0 + sub;
        if (n >= N_NODES) continue;
        float2 fA = upk2(accA[sub]);
        float2 fQ = upk2(accQ[sub]);
        float2 A;
        A.x = fA.x - fQ.x + bv.x;
        A.y = fA.y - fQ.y + bv.y;
        *(float2*)(g_A + (long)n * HID + 2 * l) = A;
        *(float2*)(g_Q + (long)n * HID + 2 * l) = fQ;
    }
}

// ---------------- edge phase: per-node max over relu(A[dst]+Q[src]) @ W2 ----------------
// warp per node (4 seq), CH=8 edges per pass, unguarded main passes.
__global__ void __launch_bounds__(256) k_edge(const float* __restrict__ W2,
                                              const float* __restrict__ b2,
                                              const float* __restrict__ Wo,
                                              const float* __restrict__ bo,
                                              float* __restrict__ out,
                                              int last) {
    __shared__ ulonglong2 W2q[32 * 32];      // 16 KB packed W2 k-pairs
    __shared__ ulonglong2 us[8][CH][32];     // 32 KB staged u (duplicated pairs)
    int tid = threadIdx.x;
    for (int i = tid; i < 1024; i += 256) {
        int k2 = i >> 5, lc = i & 31;
        const float* p0 = W2 + (2 * k2) * HID + 2 * lc;
        const float* p1 = W2 + (2 * k2 + 1) * HID + 2 * lc;
        ulonglong2 v;
        v.x = pk2(p0[0], p0[1]);
        v.y = pk2(p1[0], p1[1]);
        W2q[i] = v;
    }
    int w = tid >> 5, l = tid & 31;
    float2 b2v = *(const float2*)(b2 + 2 * l);
    float2 wo  = *(const float2*)(Wo + 2 * l);
    float  bov = bo[0];
    __syncthreads();

#pragma unroll
    for (int sub = 0; sub < 4; sub++) {
        int n = blockIdx.x * 32 + w * 4 + sub;
        if (n >= N_NODES) continue;

        int start = g_offsets[n];
        int deg = g_offsets[n + 1] - start;
        if (deg == 0 && !last) continue;

        float2 hold = *(const float2*)(g_h + (long)n * HID + 2 * l);
        float2 r = hold;

        if (deg > 0) {
            float2 a = *(const float2*)(g_A + (long)n * HID + 2 * l);
            float zmx0 = -INFINITY, zmx1 = -INFINITY;
            int nfull = deg & ~(CH - 1);

            // ---- full passes: no per-edge guards ----
            for (int c0 = 0; c0 < nfull; c0 += CH) {
                int sidx = (l < CH) ? g_csr[start + c0 + l] : 0;
#pragma unroll
                for (int e = 0; e < CH; e++) {
                    int s = __shfl_sync(0xffffffffu, sidx, e);
                    float2 b = *(const float2*)(g_Q + (long)s * HID + 2 * l);
                    float u0 = fmaxf(a.x + b.x, 0.f);
                    float u1 = fmaxf(a.y + b.y, 0.f);
                    ulonglong2 v;
                    v.x = pkdup(u0);
                    v.y = pkdup(u1);
                    us[w][e][l] = v;
                }
                __syncwarp();
                unsigned long long z[CH];
#pragma unroll
                for (int e = 0; e < CH; e++) z[e] = 0ull;
#pragma unroll 8
                for (int k2 = 0; k2 < 32; k2++) {
                    ulonglong2 wv = W2q[k2 * 32 + l];
#pragma unroll
                    for (int e = 0; e < CH; e++) {
                        ulonglong2 u = us[w][e][k2];
                        z[e] = ffma2(u.x, wv.x, z[e]);
                        z[e] = ffma2(u.y, wv.y, z[e]);
                    }
                }
                __syncwarp();
#pragma unroll
                for (int e = 0; e < CH; e++) {
                    float2 zf = upk2(z[e]);
                    zmx0 = fmaxf(zmx0, zf.x);
                    zmx1 = fmaxf(zmx1, zf.y);
                }
            }

            // ---- remainder pass (guarded) ----
            int rem = deg - nfull;
            if (rem) {
                int sidx = (l < rem) ? g_csr[start + nfull + l] : 0;
#pragma unroll
                for (int e = 0; e < CH; e++) {
                    if (e < rem) {
                        int s = __shfl_sync(0xffffffffu, sidx, e);
                        float2 b = *(const float2*)(g_Q + (long)s * HID + 2 * l);
                        float u0 = fmaxf(a.x + b.x, 0.f);
                        float u1 = fmaxf(a.y + b.y, 0.f);
                        ulonglong2 v;
                        v.x = pkdup(u0);
                        v.y = pkdup(u1);
                        us[w][e][l] = v;
                    }
                }
                __syncwarp();
                unsigned long long z[CH];
#pragma unroll
                for (int e = 0; e < CH; e++) z[e] = 0ull;
#pragma unroll 8
                for (int k2 = 0; k2 < 32; k2++) {
                    ulonglong2 wv = W2q[k2 * 32 + l];
#pragma unroll
                    for (int e = 0; e < CH; e++) {
                        ulonglong2 u = us[w][e][k2];
                        z[e] = ffma2(u.x, wv.x, z[e]);
                        z[e] = ffma2(u.y, wv.y, z[e]);
                    }
                }
                __syncwarp();
#pragma unroll
                for (int e = 0; e < CH; e++) {
                    if (e < rem) {   // discard stale-us lanes
                        float2 zf = upk2(z[e]);
                        zmx0 = fmaxf(zmx0, zf.x);
                        zmx1 = fmaxf(zmx1, zf.y);
                    }
                }
            }

            r.x = fmaxf(zmx0 + b2v.x, 0.f) + hold.x;
            r.y = fmaxf(zmx1 + b2v.y, 0.f) + hold.y;
        }

        if (last) {
            float s = fmaf(r.x, wo.x, r.y * wo.y);
#pragma unroll
            for (int o = 16; o; o >>= 1) s += __shfl_xor_sync(0xffffffffu, s, o);
            if (l == 0) out[n] = s + bov;
        } else {
            *(float2*)(g_h + (long)n * HID + 2 * l) = r;
        }
    }
}

// ---------------- launch ----------------
extern "C" void kernel_launch(void* const* d_in, const int* in_sizes, int n_in,
                              void* d_out, int out_size) {
    const float* x  = (const float*)d_in[0];
    const int*   ei = (const int*)d_in[1];
    const float* Wp = (const float*)d_in[2];
    const float* bp = (const float*)d_in[3];
    const float* W1 = (const float*)d_in[4];
    const float* b1 = (const float*)d_in[5];
    const float* W2 = (const float*)d_in[6];
    const float* b2 = (const float*)d_in[7];
    const float* Wo = (const float*)d_in[8];
    const float* bo = (const float*)d_in[9];
    float* out = (float*)d_out;

    k_zero<<<(N_NODES + 255) / 256, 256>>>(ei);
    k_hist<<<(N_EDGES + 255) / 256, 256>>>(ei);
    k_scan1<<<NSB, SCB>>>();
    k_scan2<<<1, 128>>>();
    k_scan3<<<NSB, SCB>>>();
    k_scatter<<<(N_EDGES + 255) / 256, 256>>>(ei);

    const int NB = (N_NODES + 31) / 32;
    k_proj<<<NB, 256>>>(x, Wp, bp);
    for (int l = 0; l < N_LAYERS; l++) {
        k_AQ<<<NB, 256>>>(W1 + (long)l * 2 * HID * HID, b1 + (long)l * HID);
        k_edge<<<NB, 256>>>(W2 + (long)l * HID * HID, b2 + (long)l * HID,
                            Wo, bo, out, l == N_LAYERS - 1);
    }
}

// round 8
// speedup vs baseline: 1.7068x; 1.3648x over previous
#include <cuda_runtime.h>

#define N_NODES 50000
#define N_EDGES 800000
#define IN_DIM 128
#define HID 64
#define N_LAYERS 3
#define CH 8            // edges per warp pass
#define SCB 512
#define NSB ((N_NODES + SCB - 1) / SCB)   // 98 scan blocks

// ---------------- scratch (no allocations allowed) ----------------
__device__ float g_h[N_NODES * HID];
__device__ float g_A[N_NODES * HID];   // A[dst] = h@W1a - h@W1b + b1
__device__ float g_Q[N_NODES * HID];   // Q[src] = h@W1b
__device__ int   g_counts[N_NODES];
__device__ int   g_offsets[N_NODES + 1];
__device__ int   g_cursor[N_NODES];
__device__ int   g_csr[N_EDGES];
__device__ int   g_bsum[128];
__device__ int   g_bbase[128];
__device__ int   g_is64;

// ---------------- f32x2 helpers ----------------
__device__ __forceinline__ unsigned long long pk2(float x, float y) {
    unsigned long long r;
    asm("mov.b64 %0, {%1, %2};" : "=l"(r) : "f"(x), "f"(y));
    return r;
}
__device__ __forceinline__ unsigned long long pkdup(float x) {
    unsigned long long r;
    asm("mov.b64 %0, {%1, %1};" : "=l"(r) : "f"(x));
    return r;
}
__device__ __forceinline__ float2 upk2(unsigned long long v) {
    float2 r;
    asm("mov.b64 {%0, %1}, %2;" : "=f"(r.x), "=f"(r.y) : "l"(v));
    return r;
}
__device__ __forceinline__ unsigned long long ffma2(unsigned long long a,
                                                    unsigned long long b,
                                                    unsigned long long c) {
    unsigned long long d;
    asm("fma.rn.f32x2 %0, %1, %2, %3;" : "=l"(d) : "l"(a), "l"(b), "l"(c));
    return d;
}

// ---------------- zero + dtype detect ----------------
__global__ void k_zero(const int* __restrict__ ei32) {
    int i = blockIdx.x * blockDim.x + threadIdx.x;
    if (i < N_NODES) g_counts[i] = 0;
    if (blockIdx.x == 0 && threadIdx.x == 0) {
        int z = 0;
#pragma unroll
        for (int j = 1; j < 16; j += 2) z |= ei32[j];
        g_is64 = (z == 0) ? 1 : 0;
    }
}

__device__ __forceinline__ int edge_val(const int* __restrict__ ei32, int idx, int is64) {
    return is64 ? ei32[2 * idx] : ei32[idx];
}

__global__ void k_hist(const int* __restrict__ ei32) {
    int e = blockIdx.x * blockDim.x + threadIdx.x;
    if (e < N_EDGES) {
        int d = edge_val(ei32, N_EDGES + e, g_is64);
        if ((unsigned)d < (unsigned)N_NODES) atomicAdd(&g_counts[d], 1);
    }
}

// ---------------- 3-pass scan ----------------
__device__ __forceinline__ int warp_incl_scan(int v, int lane) {
#pragma unroll
    for (int o = 1; o < 32; o <<= 1) {
        int t = __shfl_up_sync(0xffffffffu, v, o);
        if (lane >= o) v += t;
    }
    return v;
}

__global__ void __launch_bounds__(SCB) k_scan1() {
    __shared__ int ws[SCB / 32];
    int tid = threadIdx.x, lane = tid & 31, wid = tid >> 5;
    int i = blockIdx.x * SCB + tid;
    int v = (i < N_NODES) ? g_counts[i] : 0;
#pragma unroll
    for (int o = 16; o; o >>= 1) v += __shfl_xor_sync(0xffffffffu, v, o);
    if (lane == 0) ws[wid] = v;
    __syncthreads();
    if (wid == 0) {
        int s = (lane < SCB / 32) ? ws[lane] : 0;
#pragma unroll
        for (int o = 16; o; o >>= 1) s += __shfl_xor_sync(0xffffffffu, s, o);
        if (lane == 0) g_bsum[blockIdx.x] = s;
    }
}

__global__ void __launch_bounds__(128) k_scan2() {
    __shared__ int wsum[4];
    int tid = threadIdx.x, lane = tid & 31, wid = tid >> 5;
    int c = (tid < NSB) ? g_bsum[tid] : 0;
    int v = warp_incl_scan(c, lane);
    if (lane == 31) wsum[wid] = v;
    __syncthreads();
    int base = 0;
    for (int j = 0; j < wid; j++) base += wsum[j];
    v += base;
    if (tid < NSB) g_bbase[tid] = v - c;
    if (tid == NSB - 1) g_offsets[N_NODES] = v;
}

__global__ void __launch_bounds__(SCB) k_scan3() {
    __shared__ int wsum[SCB / 32];
    int tid = threadIdx.x, lane = tid & 31, wid = tid >> 5;
    int i = blockIdx.x * SCB + tid;
    int c = (i < N_NODES) ? g_counts[i] : 0;
    int v = warp_incl_scan(c, lane);
    if (lane == 31) wsum[wid] = v;
    __syncthreads();
    int base = g_bbase[blockIdx.x];
    for (int j = 0; j < wid; j++) base += wsum[j];
    int excl = base + v - c;
    if (i < N_NODES) {
        g_offsets[i] = excl;
        g_cursor[i]  = excl;
    }
}

__global__ void k_scatter(const int* __restrict__ ei32) {
    int e = blockIdx.x * blockDim.x + threadIdx.x;
    if (e < N_EDGES) {
        int is64 = g_is64;
        int d = edge_val(ei32, N_EDGES + e, is64);
        int s = edge_val(ei32, e, is64);
        if ((unsigned)d < (unsigned)N_NODES && (unsigned)s < (unsigned)N_NODES) {
            int pos = atomicAdd(&g_cursor[d], 1);
            g_csr[pos] = s;
        }
    }
}

// ---------------- input projection: h = x @ Wp + bp ----------------
__global__ void __launch_bounds__(256) k_proj(const float* __restrict__ x,
                                              const float* __restrict__ Wp,
                                              const float* __restrict__ bp) {
    __shared__ unsigned long long Wsp[IN_DIM * 32];  // 32 KB packed pairs
    __shared__ float xs[32][IN_DIM];                 // 16 KB
    int tid = threadIdx.x;
    for (int i = tid; i < IN_DIM * 32; i += 256) {
        int k = i >> 5, lc = i & 31;
        Wsp[i] = pk2(Wp[k * HID + 2 * lc], Wp[k * HID + 2 * lc + 1]);
    }
    int w = tid >> 5, l = tid & 31;
    int m0 = w * 4;
#pragma unroll
    for (int sub = 0; sub < 4; sub++) {
        int n = blockIdx.x * 32 + m0 + sub;
        if (n < N_NODES)
            ((float4*)xs[m0 + sub])[l] = ((const float4*)(x + (long)n * IN_DIM))[l];
    }
    __syncthreads();
    unsigned long long bv = pk2(bp[2 * l], bp[2 * l + 1]);
    unsigned long long acc[4] = {bv, bv, bv, bv};
#pragma unroll 4
    for (int k = 0; k < IN_DIM; k++) {
        unsigned long long wv = Wsp[k * 32 + l];
#pragma unroll
        for (int sub = 0; sub < 4; sub++) {
            unsigned long long xk2 = pkdup(xs[m0 + sub][k]);
            acc[sub] = ffma2(xk2, wv, acc[sub]);
        }
    }
#pragma unroll
    for (int sub = 0; sub < 4; sub++) {
        int n = blockIdx.x * 32 + m0 + sub;
        if (n < N_NODES)
            *(float2*)(g_h + (long)n * HID + 2 * l) = upk2(acc[sub]);
    }
}

// ---------------- node GEMMs: A = h@W1a - h@W1b + b1 ; Q = h@W1b ----------------
__global__ void __launch_bounds__(256) k_AQ(const float* __restrict__ W1,
                                            const float* __restrict__ b1) {
    __shared__ unsigned long long Wsa[HID * 32];  // 16 KB
    __shared__ unsigned long long Wsb[HID * 32];  // 16 KB
    __shared__ float hs[32][HID];                 // 8 KB
    int tid = threadIdx.x;
    for (int i = tid; i < HID * 32; i += 256) {
        int k = i >> 5, lc = i & 31;
        Wsa[i] = pk2(W1[k * HID + 2 * lc], W1[k * HID + 2 * lc + 1]);
        Wsb[i] = pk2(W1[(HID + k) * HID + 2 * lc], W1[(HID + k) * HID + 2 * lc + 1]);
    }
    int w = tid >> 5, l = tid & 31;
    int m0 = w * 4;
#pragma unroll
    for (int sub = 0; sub < 4; sub++) {
        int n = blockIdx.x * 32 + m0 + sub;
        if (n < N_NODES)
            ((float2*)hs[m0 + sub])[l] = *(const float2*)(g_h + (long)n * HID + 2 * l);
    }
    __syncthreads();
    unsigned long long accA[4] = {0ull, 0ull, 0ull, 0ull};
    unsigned long long accQ[4] = {0ull, 0ull, 0ull, 0ull};
#pragma unroll 4
    for (int k = 0; k < HID; k++) {
        unsigned long long wa = Wsa[k * 32 + l];
        unsigned long long wb = Wsb[k * 32 + l];
#pragma unroll
        for (int sub = 0; sub < 4; sub++) {
            unsigned long long hk2 = pkdup(hs[m0 + sub][k]);
            accA[sub] = ffma2(hk2, wa, accA[sub]);
            accQ[sub] = ffma2(hk2, wb, accQ[sub]);
        }
    }
    float2 bv = *(const float2*)(b1 + 2 * l);
#pragma unroll
    for (int sub = 0; sub < 4; sub++) {
        int n = blockIdx.x * 32 + m0 + sub;
        if (n >= N_NODES) continue;
        float2 fA = upk2(accA[sub]);
        float2 fQ = upk2(accQ[sub]);
        float2 A;
        A.x = fA.x - fQ.x + bv.x;
        A.y = fA.y - fQ.y + bv.y;
        *(float2*)(g_A + (long)n * HID + 2 * l) = A;
        *(float2*)(g_Q + (long)n * HID + 2 * l) = fQ;
    }
}

// ---------------- edge phase: per-node max over relu(A[dst]+Q[src]) @ W2 ----------------
// Col-split packing: one 16B us read serves 2 edges; W2 packed column-major pairs.
// z[col 2l]  = hadd(zA): zA += (u[2k2],u[2k2+1]) * (W2[2k2][2l],  W2[2k2+1][2l])
// z[col 2l+1]= hadd(zB): zB += (u[2k2],u[2k2+1]) * (W2[2k2][2l+1],W2[2k2+1][2l+1])
#define USTRIDE 10   // ulonglongs per k2 row (80B: 16B-aligned reads, 4-way STS conflicts)
__global__ void __launch_bounds__(256) k_edge(const float* __restrict__ W2,
                                              const float* __restrict__ b2,
                                              const float* __restrict__ Wo,
                                              const float* __restrict__ bo,
                                              float* __restrict__ out,
                                              int last) {
    __shared__ ulonglong2 W2c[32 * 32];                      // 16 KB col-pair packed
    __shared__ unsigned long long us2[8][32 * USTRIDE];      // 20 KB
    int tid = threadIdx.x;
    for (int i = tid; i < 1024; i += 256) {
        int k2 = i >> 5, lc = i & 31;
        const float* r0 = W2 + (2 * k2) * HID;
        const float* r1 = W2 + (2 * k2 + 1) * HID;
        ulonglong2 v;
        v.x = pk2(r0[2 * lc],     r1[2 * lc]);       // col 2lc, k-pair
        v.y = pk2(r0[2 * lc + 1], r1[2 * lc + 1]);   // col 2lc+1, k-pair
        W2c[i] = v;
    }
    int w = tid >> 5, l = tid & 31;
    unsigned long long* usw = us2[w];
    float2 b2v = *(const float2*)(b2 + 2 * l);
    float2 wo  = *(const float2*)(Wo + 2 * l);
    float  bov = bo[0];
    __syncthreads();

#pragma unroll
    for (int sub = 0; sub < 4; sub++) {
        int n = blockIdx.x * 32 + w * 4 + sub;
        if (n >= N_NODES) continue;

        int start = g_offsets[n];
        int deg = g_offsets[n + 1] - start;
        if (deg == 0 && !last) continue;

        float2 hold = *(const float2*)(g_h + (long)n * HID + 2 * l);
        float2 r = hold;

        if (deg > 0) {
            float2 a = *(const float2*)(g_A + (long)n * HID + 2 * l);
            float zmx0 = -INFINITY, zmx1 = -INFINITY;
            int nfull = deg & ~(CH - 1);

            // ---- full passes ----
            for (int c0 = 0; c0 < nfull; c0 += CH) {
                int sidx = (l < CH) ? g_csr[start + c0 + l] : 0;
#pragma unroll
                for (int e = 0; e < CH; e++) {
                    int s = __shfl_sync(0xffffffffu, sidx, e);
                    float2 b = *(const float2*)(g_Q + (long)s * HID + 2 * l);
                    float u0 = fmaxf(a.x + b.x, 0.f);
                    float u1 = fmaxf(a.y + b.y, 0.f);
                    usw[l * USTRIDE + (e >> 1) * 2 + (e & 1)] = pk2(u0, u1);
                }
                __syncwarp();
                unsigned long long zA[CH], zB[CH];
#pragma unroll
                for (int e = 0; e < CH; e++) { zA[e] = 0ull; zB[e] = 0ull; }
#pragma unroll 8
                for (int k2 = 0; k2 < 32; k2++) {
                    ulonglong2 wv = W2c[k2 * 32 + l];
#pragma unroll
                    for (int ep = 0; ep < CH / 2; ep++) {
                        ulonglong2 uu = *(const ulonglong2*)(usw + k2 * USTRIDE + ep * 2);
                        zA[2 * ep]     = ffma2(uu.x, wv.x, zA[2 * ep]);
                        zB[2 * ep]     = ffma2(uu.x, wv.y, zB[2 * ep]);
                        zA[2 * ep + 1] = ffma2(uu.y, wv.x, zA[2 * ep + 1]);
                        zB[2 * ep + 1] = ffma2(uu.y, wv.y, zB[2 * ep + 1]);
                    }
                }
                __syncwarp();
#pragma unroll
                for (int e = 0; e < CH; e++) {
                    float2 fa = upk2(zA[e]);
                    float2 fb = upk2(zB[e]);
                    zmx0 = fmaxf(zmx0, fa.x + fa.y);
                    zmx1 = fmaxf(zmx1, fb.x + fb.y);
                }
            }

            // ---- remainder pass (guarded; stale partner slots discarded at max) ----
            int rem = deg - nfull;
            if (rem) {
                int sidx = (l < rem) ? g_csr[start + nfull + l] : 0;
#pragma unroll
                for (int e = 0; e < CH; e++) {
                    if (e < rem) {
                        int s = __shfl_sync(0xffffffffu, sidx, e);
                        float2 b = *(const float2*)(g_Q + (long)s * HID + 2 * l);
                        float u0 = fmaxf(a.x + b.x, 0.f);
                        float u1 = fmaxf(a.y + b.y, 0.f);
                        usw[l * USTRIDE + (e >> 1) * 2 + (e & 1)] = pk2(u0, u1);
                    }
                }
                __syncwarp();
                unsigned long long zA[CH], zB[CH];
#pragma unroll
                for (int e = 0; e < CH; e++) { zA[e] = 0ull; zB[e] = 0ull; }
#pragma unroll 8
                for (int k2 = 0; k2 < 32; k2++) {
                    ulonglong2 wv = W2c[k2 * 32 + l];
#pragma unroll
                    for (int ep = 0; ep < CH / 2; ep++) {
                        ulonglong2 uu = *(const ulonglong2*)(usw + k2 * USTRIDE + ep * 2);
                        zA[2 * ep]     = ffma2(uu.x, wv.x, zA[2 * ep]);
                        zB[2 * ep]     = ffma2(uu.x, wv.y, zB[2 * ep]);
                        zA[2 * ep + 1] = ffma2(uu.y, wv.x, zA[2 * ep + 1]);
                        zB[2 * ep + 1] = ffma2(uu.y, wv.y, zB[2 * ep + 1]);
                    }
                }
                __syncwarp();
#pragma unroll
                for (int e = 0; e < CH; e++) {
                    if (e < rem) {
                        float2 fa = upk2(zA[e]);
                        float2 fb = upk2(zB[e]);
                        zmx0 = fmaxf(zmx0, fa.x + fa.y);
                        zmx1 = fmaxf(zmx1, fb.x + fb.y);
                    }
                }
            }

            r.x = fmaxf(zmx0 + b2v.x, 0.f) + hold.x;
            r.y = fmaxf(zmx1 + b2v.y, 0.f) + hold.y;
        }

        if (last) {
            float s = fmaf(r.x, wo.x, r.y * wo.y);
#pragma unroll
            for (int o = 16; o; o >>= 1) s += __shfl_xor_sync(0xffffffffu, s, o);
            if (l == 0) out[n] = s + bov;
        } else {
            *(float2*)(g_h + (long)n * HID + 2 * l) = r;
        }
    }
}

// ---------------- launch ----------------
extern "C" void kernel_launch(void* const* d_in, const int* in_sizes, int n_in,
                              void* d_out, int out_size) {
    const float* x  = (const float*)d_in[0];
    const int*   ei = (const int*)d_in[1];
    const float* Wp = (const float*)d_in[2];
    const float* bp = (const float*)d_in[3];
    const float* W1 = (const float*)d_in[4];
    const float* b1 = (const float*)d_in[5];
    const float* W2 = (const float*)d_in[6];
    const float* b2 = (const float*)d_in[7];
    const float* Wo = (const float*)d_in[8];
    const float* bo = (const float*)d_in[9];
    float* out = (float*)d_out;

    k_zero<<<(N_NODES + 255) / 256, 256>>>(ei);
    k_hist<<<(N_EDGES + 255) / 256, 256>>>(ei);
    k_scan1<<<NSB, SCB>>>();
    k_scan2<<<1, 128>>>();
    k_scan3<<<NSB, SCB>>>();
    k_scatter<<<(N_EDGES + 255) / 256, 256>>>(ei);

    const int NB = (N_NODES + 31) / 32;
    k_proj<<<NB, 256>>>(x, Wp, bp);
    for (int l = 0; l < N_LAYERS; l++) {
        k_AQ<<<NB, 256>>>(W1 + (long)l * 2 * HID * HID, b1 + (long)l * HID);
        k_edge<<<NB, 256>>>(W2 + (long)l * HID * HID, b2 + (long)l * HID,
                            Wo, bo, out, l == N_LAYERS - 1);
    }
}

// round 11
// speedup vs baseline: 1.8394x; 1.0777x over previous
#include <cuda_runtime.h>
#include <cuda_bf16.h>
#include <cstdint>

#define N_NODES 50000
#define N_EDGES 800000
#define IN_DIM 128
#define HID 64
#define N_LAYERS 3
#define SCB 512
#define NSB ((N_NODES + SCB - 1) / SCB)

#define NT_W (N_EDGES / 32)          // 25000 warp-tiles, exact
#define EMMA_BLOCKS 592

// ---- dynamic SMEM layout for k_edgemma (49152 = 48KB exactly, NO static shared) ----
#define SM_U    0        // 4 warps x 8KB stripe: Uhi 4KB + Ulo 4KB (union zbuf 32x64 f32)
#define SM_WHI  32768    // W2 bf16 hi  [k][n] swizzled, 8KB
#define SM_WLO  40960    // W2 bf16 lo, 8KB
#define SMEM_DYN 49152

// ---------------- scratch ----------------
__device__ float g_h[N_NODES * HID];
__device__ float g_A[N_NODES * HID];
__device__ float g_Q[N_NODES * HID];
__device__ unsigned g_z[N_NODES * HID];     // ordered-encoded max accumulator
__device__ int   g_counts[N_NODES];
__device__ int   g_offsets[N_NODES + 1];
__device__ int   g_cursor[N_NODES];
__device__ int   g_csr[N_EDGES];
__device__ int   g_csr_dst[N_EDGES];
__device__ int   g_bsum[128];
__device__ int   g_bbase[128];
__device__ int   g_is64;
__device__ unsigned g_W2t_hi[N_LAYERS * 64 * 32];   // [L][k][n2] bf16x2
__device__ unsigned g_W2t_lo[N_LAYERS * 64 * 32];

// ---------------- helpers ----------------
__device__ __forceinline__ unsigned long long pk2(float x, float y) {
    unsigned long long r;
    asm("mov.b64 %0, {%1, %2};" : "=l"(r) : "f"(x), "f"(y));
    return r;
}
__device__ __forceinline__ unsigned long long pkdup(float x) {
    unsigned long long r;
    asm("mov.b64 %0, {%1, %1};" : "=l"(r) : "f"(x));
    return r;
}
__device__ __forceinline__ float2 upk2(unsigned long long v) {
    float2 r;
    asm("mov.b64 {%0, %1}, %2;" : "=f"(r.x), "=f"(r.y) : "l"(v));
    return r;
}
__device__ __forceinline__ unsigned long long ffma2(unsigned long long a,
                                                    unsigned long long b,
                                                    unsigned long long c) {
    unsigned long long d;
    asm("fma.rn.f32x2 %0, %1, %2, %3;" : "=l"(d) : "l"(a), "l"(b), "l"(c));
    return d;
}
__device__ __forceinline__ uint32_t smem_u32(const void* p) {
    uint32_t a;
    asm("{ .reg .u64 t; cvta.to.shared.u64 t, %1; cvt.u32.u64 %0, t; }" : "=r"(a) : "l"(p));
    return a;
}
__device__ __forceinline__ unsigned encf(float f) {
    unsigned u = __float_as_uint(f);
    return (u & 0x80000000u) ? ~u : (u | 0x80000000u);
}
__device__ __forceinline__ float decf(unsigned u) {
    return (u & 0x80000000u) ? __uint_as_float(u & 0x7FFFFFFFu) : __uint_as_float(~u);
}

// ---- warp-MMA primitives (base-target legal: sm_80+) ----
__device__ __forceinline__ void ldsm4(uint32_t* r, uint32_t a) {
    asm volatile("ldmatrix.sync.aligned.m8n8.x4.shared.b16 {%0,%1,%2,%3}, [%4];"
        : "=r"(r[0]), "=r"(r[1]), "=r"(r[2]), "=r"(r[3]) : "r"(a));
}
__device__ __forceinline__ void ldsm4t(uint32_t* r, uint32_t a) {
    asm volatile("ldmatrix.sync.aligned.m8n8.x4.trans.shared.b16 {%0,%1,%2,%3}, [%4];"
        : "=r"(r[0]), "=r"(r[1]), "=r"(r[2]), "=r"(r[3]) : "r"(a));
}
__device__ __forceinline__ void mma16816(float* d, const uint32_t* a, uint32_t b0, uint32_t b1) {
    asm volatile("mma.sync.aligned.m16n8k16.row.col.f32.bf16.bf16.f32 "
        "{%0,%1,%2,%3}, {%4,%5,%6,%7}, {%8,%9}, {%0,%1,%2,%3};"
        : "+f"(d[0]), "+f"(d[1]), "+f"(d[2]), "+f"(d[3])
        : "r"(a[0]), "r"(a[1]), "r"(a[2]), "r"(a[3]), "r"(b0), "r"(b1));
}

// ---------------- CSR build ----------------
__global__ void k_zero(const int* __restrict__ ei32) {
    int i = blockIdx.x * blockDim.x + threadIdx.x;
    if (i < N_NODES) g_counts[i] = 0;
    if (blockIdx.x == 0 && threadIdx.x == 0) {
        int z = 0;
#pragma unroll
        for (int j = 1; j < 16; j += 2) z |= ei32[j];
        g_is64 = (z == 0) ? 1 : 0;
    }
}
__device__ __forceinline__ int edge_val(const int* __restrict__ e, int i, int is64) {
    return is64 ? e[2 * i] : e[i];
}
__global__ void k_hist(const int* __restrict__ ei32) {
    int e = blockIdx.x * blockDim.x + threadIdx.x;
    if (e < N_EDGES) {
        int d = edge_val(ei32, N_EDGES + e, g_is64);
        if ((unsigned)d < (unsigned)N_NODES) atomicAdd(&g_counts[d], 1);
    }
}
__device__ __forceinline__ int warp_incl_scan(int v, int lane) {
#pragma unroll
    for (int o = 1; o < 32; o <<= 1) {
        int t = __shfl_up_sync(0xffffffffu, v, o);
        if (lane >= o) v += t;
    }
    return v;
}
__global__ void __launch_bounds__(SCB) k_scan1() {
    __shared__ int ws[SCB / 32];
    int tid = threadIdx.x, lane = tid & 31, wid = tid >> 5;
    int i = blockIdx.x * SCB + tid;
    int v = (i < N_NODES) ? g_counts[i] : 0;
#pragma unroll
    for (int o = 16; o; o >>= 1) v += __shfl_xor_sync(0xffffffffu, v, o);
    if (lane == 0) ws[wid] = v;
    __syncthreads();
    if (wid == 0) {
        int s = (lane < SCB / 32) ? ws[lane] : 0;
#pragma unroll
        for (int o = 16; o; o >>= 1) s += __shfl_xor_sync(0xffffffffu, s, o);
        if (lane == 0) g_bsum[blockIdx.x] = s;
    }
}
__global__ void __launch_bounds__(128) k_scan2() {
    __shared__ int wsum[4];
    int tid = threadIdx.x, lane = tid & 31, wid = tid >> 5;
    int c = (tid < NSB) ? g_bsum[tid] : 0;
    int v = warp_incl_scan(c, lane);
    if (lane == 31) wsum[wid] = v;
    __syncthreads();
    int base = 0;
    for (int j = 0; j < wid; j++) base += wsum[j];
    v += base;
    if (tid < NSB) g_bbase[tid] = v - c;
    if (tid == NSB - 1) g_offsets[N_NODES] = v;
}
__global__ void __launch_bounds__(SCB) k_scan3() {
    __shared__ int wsum[SCB / 32];
    int tid = threadIdx.x, lane = tid & 31, wid = tid >> 5;
    int i = blockIdx.x * SCB + tid;
    int c = (i < N_NODES) ? g_counts[i] : 0;
    int v = warp_incl_scan(c, lane);
    if (lane == 31) wsum[wid] = v;
    __syncthreads();
    int base = g_bbase[blockIdx.x];
    for (int j = 0; j < wid; j++) base += wsum[j];
    int excl = base + v - c;
    if (i < N_NODES) {
        g_offsets[i] = excl;
        g_cursor[i]  = excl;
    }
}
__global__ void k_scatter(const int* __restrict__ ei32) {
    int e = blockIdx.x * blockDim.x + threadIdx.x;
    if (e < N_EDGES) {
        int is64 = g_is64;
        int d = edge_val(ei32, N_EDGES + e, is64);
        int s = edge_val(ei32, e, is64);
        if ((unsigned)d < (unsigned)N_NODES && (unsigned)s < (unsigned)N_NODES) {
            int pos = atomicAdd(&g_cursor[d], 1);
            g_csr[pos] = s;
            g_csr_dst[pos] = d;
        }
    }
}

// ---------------- W2 bf16 hi/lo precompute: [L][k][n2] ----------------
__global__ void k_w2cvt(const float* __restrict__ W2) {
    int i = blockIdx.x * blockDim.x + threadIdx.x;
    if (i >= N_LAYERS * 64 * 32) return;
    int L = i / 2048, rem = i % 2048;
    int k = rem >> 5, n2 = rem & 31;
    const float* WL = W2 + L * HID * HID;
    float f0 = WL[k * HID + 2 * n2];
    float f1 = WL[k * HID + 2 * n2 + 1];
    __nv_bfloat162 hb = __floats2bfloat162_rn(f0, f1);
    float h0 = __bfloat162float(hb.x), h1 = __bfloat162float(hb.y);
    __nv_bfloat162 lb = __floats2bfloat162_rn(f0 - h0, f1 - h1);
    g_W2t_hi[i] = *reinterpret_cast<unsigned*>(&hb);
    g_W2t_lo[i] = *reinterpret_cast<unsigned*>(&lb);
}

__global__ void k_zinit() {
    int i = blockIdx.x * blockDim.x + threadIdx.x;
    if (i < N_NODES * HID) g_z[i] = 0u;
}

// ---------------- input projection ----------------
__global__ void __launch_bounds__(256) k_proj(const float* __restrict__ x,
                                              const float* __restrict__ Wp,
                                              const float* __restrict__ bp) {
    __shared__ unsigned long long Wsp[IN_DIM * 32];
    __shared__ float xs[32][IN_DIM];
    int tid = threadIdx.x;
    for (int i = tid; i < IN_DIM * 32; i += 256) {
        int k = i >> 5, lc = i & 31;
        Wsp[i] = pk2(Wp[k * HID + 2 * lc], Wp[k * HID + 2 * lc + 1]);
    }
    int w = tid >> 5, l = tid & 31;
    int m0 = w * 4;
#pragma unroll
    for (int sub = 0; sub < 4; sub++) {
        int n = blockIdx.x * 32 + m0 + sub;
        if (n < N_NODES)
            ((float4*)xs[m0 + sub])[l] = ((const float4*)(x + (long)n * IN_DIM))[l];
    }
    __syncthreads();
    unsigned long long bv = pk2(bp[2 * l], bp[2 * l + 1]);
    unsigned long long acc[4] = {bv, bv, bv, bv};
#pragma unroll 4
    for (int k = 0; k < IN_DIM; k++) {
        unsigned long long wv = Wsp[k * 32 + l];
#pragma unroll
        for (int sub = 0; sub < 4; sub++)
            acc[sub] = ffma2(pkdup(xs[m0 + sub][k]), wv, acc[sub]);
    }
#pragma unroll
    for (int sub = 0; sub < 4; sub++) {
        int n = blockIdx.x * 32 + m0 + sub;
        if (n < N_NODES)
            *(float2*)(g_h + (long)n * HID + 2 * l) = upk2(acc[sub]);
    }
}

// ---------------- node GEMMs ----------------
__global__ void __launch_bounds__(256) k_AQ(const float* __restrict__ W1,
                                            const float* __restrict__ b1) {
    __shared__ unsigned long long Wsa[HID * 32];
    __shared__ unsigned long long Wsb[HID * 32];
    __shared__ float hs[32][HID];
    int tid = threadIdx.x;
    for (int i = tid; i < HID * 32; i += 256) {
        int k = i >> 5, lc = i & 31;
        Wsa[i] = pk2(W1[k * HID + 2 * lc], W1[k * HID + 2 * lc + 1]);
        Wsb[i] = pk2(W1[(HID + k) * HID + 2 * lc], W1[(HID + k) * HID + 2 * lc + 1]);
    }
    int w = tid >> 5, l = tid & 31;
    int m0 = w * 4;
#pragma unroll
    for (int sub = 0; sub < 4; sub++) {
        int n = blockIdx.x * 32 + m0 + sub;
        if (n < N_NODES)
            ((float2*)hs[m0 + sub])[l] = *(const float2*)(g_h + (long)n * HID + 2 * l);
    }
    __syncthreads();
    unsigned long long accA[4] = {0ull, 0ull, 0ull, 0ull};
    unsigned long long accQ[4] = {0ull, 0ull, 0ull, 0ull};
#pragma unroll 4
    for (int k = 0; k < HID; k++) {
        unsigned long long wa = Wsa[k * 32 + l];
        unsigned long long wb = Wsb[k * 32 + l];
#pragma unroll
        for (int sub = 0; sub < 4; sub++) {
            unsigned long long hk2 = pkdup(hs[m0 + sub][k]);
            accA[sub] = ffma2(hk2, wa, accA[sub]);
            accQ[sub] = ffma2(hk2, wb, accQ[sub]);
        }
    }
    float2 bv = *(const float2*)(b1 + 2 * l);
#pragma unroll
    for (int sub = 0; sub < 4; sub++) {
        int n = blockIdx.x * 32 + m0 + sub;
        if (n >= N_NODES) continue;
        float2 fA = upk2(accA[sub]);
        float2 fQ = upk2(accQ[sub]);
        float2 A;
        A.x = fA.x - fQ.x + bv.x;
        A.y = fA.y - fQ.y + bv.y;
        *(float2*)(g_A + (long)n * HID + 2 * l) = A;
        *(float2*)(g_Q + (long)n * HID + 2 * l) = fQ;
    }
}

// ---------------- HMMA edge phase ----------------
// Warp-autonomous 32-edge tiles: stage U=relu(A+Q) bf16 hi/lo (swizzled),
// 3-term m16n8k16 bf16 MMA (Uhi*Whi + Uhi*Wlo + Ulo*Whi), segmented max -> g_z.
// dst/src indices held in registers + shuffles (no static shared).
__global__ void __launch_bounds__(128) k_edgemma(int layer) {
    extern __shared__ char sm[];
    uint32_t smb = smem_u32(sm);
    int tid = threadIdx.x, w = tid >> 5, l = tid & 31;

    // load W2 bf16 [k][n] swizzled: word n2 of row k at k*128 + ((n2*4) ^ ((k&7)<<4))
    const unsigned* wh = g_W2t_hi + layer * 2048;
    const unsigned* wl = g_W2t_lo + layer * 2048;
    for (int i = tid; i < 2048; i += 128) {
        int k = i >> 5, n2 = i & 31;
        uint32_t off = (uint32_t)(k * 128 + ((n2 * 4) ^ ((k & 7) << 4)));
        *(unsigned*)(sm + SM_WHI + off) = wh[i];
        *(unsigned*)(sm + SM_WLO + off) = wl[i];
    }
    __syncthreads();

    char* uw = sm + SM_U + w * 8192;        // Uhi 4KB | Ulo 4KB (union zbuf 8KB)
    uint32_t uw32 = smb + SM_U + w * 8192;
    float* zb = (float*)uw;

    // ldmatrix lane addressing
    int lrow = l & 7;
    int arow = ((l >> 3) & 1) * 8 + lrow;    // 0..15
    int kgrp = l >> 4;                        // 0..1
    uint32_t a_base0 = uw32 + arow * 128;
    uint32_t w_hi_base = smb + SM_WHI + arow * 128;
    uint32_t w_lo_base = smb + SM_WLO + arow * 128;

    for (int wt = blockIdx.x * 4 + w; wt < NT_W; wt += gridDim.x * 4) {
        int tbase = wt * 32;

        // coalesced per-lane edge indices for this tile
        int mysrc = g_csr[tbase + l];
        int mydst = g_csr_dst[tbase + l];

        // ---- stage 32 edges ----
        {
            int prev_dst = -1;
            float2 a2 = make_float2(0.f, 0.f);
            for (int rr = 0; rr < 32; rr++) {
                int src = __shfl_sync(0xffffffffu, mysrc, rr);
                int dst = __shfl_sync(0xffffffffu, mydst, rr);
                if (dst != prev_dst) {
                    a2 = *(const float2*)(g_A + (long)dst * HID + 2 * l);
                    prev_dst = dst;
                }
                float2 q2 = *(const float2*)(g_Q + (long)src * HID + 2 * l);
                float u0 = fmaxf(a2.x + q2.x, 0.f);
                float u1 = fmaxf(a2.y + q2.y, 0.f);
                __nv_bfloat162 hb = __floats2bfloat162_rn(u0, u1);
                float h0 = __bfloat162float(hb.x), h1 = __bfloat162float(hb.y);
                __nv_bfloat162 lb = __floats2bfloat162_rn(u0 - h0, u1 - h1);
                uint32_t off = (uint32_t)(rr * 128 + ((l * 4) ^ ((rr & 7) << 4)));
                *(unsigned*)(uw + off) = *reinterpret_cast<unsigned*>(&hb);
                *(unsigned*)(uw + 4096 + off) = *reinterpret_cast<unsigned*>(&lb);
            }
        }
        __syncwarp();

        // ---- MMA: d[2 rb][8 nb][4] ----
        float d[2][8][4];
#pragma unroll
        for (int rb = 0; rb < 2; rb++)
#pragma unroll
            for (int nb = 0; nb < 8; nb++)
#pragma unroll
                for (int j = 0; j < 4; j++) d[rb][nb][j] = 0.f;

#pragma unroll
        for (int ks = 0; ks < 4; ks++) {
            uint32_t axor = (uint32_t)(((ks * 2 + kgrp) ^ lrow) << 4);
            uint32_t ah[2][4], al[2][4];
            ldsm4(ah[0], a_base0 + axor);
            ldsm4(ah[1], a_base0 + 2048 + axor);
            ldsm4(al[0], a_base0 + 4096 + axor);
            ldsm4(al[1], a_base0 + 6144 + axor);
#pragma unroll
            for (int np = 0; np < 4; np++) {
                uint32_t bxor = (uint32_t)(((np * 2 + kgrp) ^ lrow) << 4);
                uint32_t bh[4], bl[4];
                ldsm4t(bh, w_hi_base + ks * 2048 + bxor);
                ldsm4t(bl, w_lo_base + ks * 2048 + bxor);
#pragma unroll
                for (int rb = 0; rb < 2; rb++) {
                    mma16816(d[rb][2 * np],     ah[rb], bh[0], bh[1]);
                    mma16816(d[rb][2 * np + 1], ah[rb], bh[2], bh[3]);
                    mma16816(d[rb][2 * np],     ah[rb], bl[0], bl[1]);
                    mma16816(d[rb][2 * np + 1], ah[rb], bl[2], bl[3]);
                    mma16816(d[rb][2 * np],     al[rb], bh[0], bh[1]);
                    mma16816(d[rb][2 * np + 1], al[rb], bh[2], bh[3]);
                }
            }
        }
        __syncwarp();   // all ldmatrix reads done before zbuf overwrite

        // ---- D -> zbuf (swizzled rows: word c at r*64 + (c ^ ((r&7)<<3))) ----
#pragma unroll
        for (int rb = 0; rb < 2; rb++) {
#pragma unroll
            for (int nb = 0; nb < 8; nb++) {
                int c0 = nb * 8 + (l & 3) * 2;
                int r0 = rb * 16 + (l >> 2);
                int r1 = r0 + 8;
                *(float2*)&zb[r0 * 64 + (c0 ^ ((r0 & 7) << 3))] =
                    make_float2(d[rb][nb][0], d[rb][nb][1]);
                *(float2*)&zb[r1 * 64 + (c0 ^ ((r1 & 7) << 3))] =
                    make_float2(d[rb][nb][2], d[rb][nb][3]);
            }
        }
        __syncwarp();

        // ---- segmented max + encoded atomicMax (lane owns cols 2l, 2l+1) ----
        {
            float m0 = -INFINITY, m1 = -INFINITY;
            int prev = __shfl_sync(0xffffffffu, mydst, 0);
            for (int rr = 0; rr < 32; rr++) {
                int dcur = __shfl_sync(0xffffffffu, mydst, rr);
                if (dcur != prev) {
                    atomicMax(&g_z[(long)prev * HID + 2 * l], encf(m0));
                    atomicMax(&g_z[(long)prev * HID + 2 * l + 1], encf(m1));
                    m0 = -INFINITY; m1 = -INFINITY;
                    prev = dcur;
                }
                float2 zv = *(const float2*)&zb[rr * 64 + ((2 * l) ^ ((rr & 7) << 3))];
                m0 = fmaxf(m0, zv.x);
                m1 = fmaxf(m1, zv.y);
            }
            atomicMax(&g_z[(long)prev * HID + 2 * l], encf(m0));
            atomicMax(&g_z[(long)prev * HID + 2 * l + 1], encf(m1));
        }
        __syncwarp();
    }
}

// ---------------- finish: h += relu(max + b2); last layer emits output; resets z ----
__global__ void __launch_bounds__(256) k_finish(const float* __restrict__ b2,
                                                const float* __restrict__ Wo,
                                                const float* __restrict__ bo,
                                                float* __restrict__ out,
                                                int last) {
    int w = threadIdx.x >> 5, l = threadIdx.x & 31;
    int n = blockIdx.x * 8 + w;
    if (n >= N_NODES) return;
    int deg = g_offsets[n + 1] - g_offsets[n];
    float2 hold = *(const float2*)(g_h + (long)n * HID + 2 * l);
    float2 r = hold;
    if (deg > 0) {
        unsigned e0 = g_z[(long)n * HID + 2 * l];
        unsigned e1 = g_z[(long)n * HID + 2 * l + 1];
        float2 b2v = *(const float2*)(b2 + 2 * l);
        r.x = fmaxf(decf(e0) + b2v.x, 0.f) + hold.x;
        r.y = fmaxf(decf(e1) + b2v.y, 0.f) + hold.y;
        g_z[(long)n * HID + 2 * l] = 0u;
        g_z[(long)n * HID + 2 * l + 1] = 0u;
    }
    if (last) {
        float2 wo = *(const float2*)(Wo + 2 * l);
        float s = fmaf(r.x, wo.x, r.y * wo.y);
#pragma unroll
        for (int o = 16; o; o >>= 1) s += __shfl_xor_sync(0xffffffffu, s, o);
        if (l == 0) out[n] = s + bo[0];
    } else {
        *(float2*)(g_h + (long)n * HID + 2 * l) = r;
    }
}

// ---------------- launch ----------------
extern "C" void kernel_launch(void* const* d_in, const int* in_sizes, int n_in,
                              void* d_out, int out_size) {
    const float* x  = (const float*)d_in[0];
    const int*   ei = (const int*)d_in[1];
    const float* Wp = (const float*)d_in[2];
    const float* bp = (const float*)d_in[3];
    const float* W1 = (const float*)d_in[4];
    const float* b1 = (const float*)d_in[5];
    const float* W2 = (const float*)d_in[6];
    const float* b2 = (const float*)d_in[7];
    const float* Wo = (const float*)d_in[8];
    const float* bo = (const float*)d_in[9];
    float* out = (float*)d_out;

    k_zero<<<(N_NODES + 255) / 256, 256>>>(ei);
    k_hist<<<(N_EDGES + 255) / 256, 256>>>(ei);
    k_scan1<<<NSB, SCB>>>();
    k_scan2<<<1, 128>>>();
    k_scan3<<<NSB, SCB>>>();
    k_scatter<<<(N_EDGES + 255) / 256, 256>>>(ei);

    k_w2cvt<<<(N_LAYERS * 64 * 32 + 255) / 256, 256>>>(W2);
    k_zinit<<<(N_NODES * HID + 1023) / 1024, 1024>>>();

    const int NB = (N_NODES + 31) / 32;
    k_proj<<<NB, 256>>>(x, Wp, bp);
    for (int L = 0; L < N_LAYERS; L++) {
        k_AQ<<<NB, 256>>>(W1 + (long)L * 2 * HID * HID, b1 + (long)L * HID);
        k_edgemma<<<EMMA_BLOCKS, 128, SMEM_DYN>>>(L);
        k_finish<<<(N_NODES + 7) / 8, 256>>>(b2 + (long)L * HID, Wo, bo, out,
                                             L == N_LAYERS - 1);
    }
}

// round 12
// speedup vs baseline: 3.1076x; 1.6895x over previous
#include <cuda_runtime.h>
#include <cuda_fp16.h>
#include <cstdint>
#include <climits>

#define N_NODES 50000
#define N_EDGES 800000
#define IN_DIM 128
#define HID 64
#define N_LAYERS 3
#define SCB 512
#define NSB ((N_NODES + SCB - 1) / SCB)

#define NT_W (N_EDGES / 32)          // 25000 warp-tiles, exact
#define EMMA_BLOCKS 592
#define TW_TOT (EMMA_BLOCKS * 4)

// ---- dynamic SMEM layout for k_edgemma (48KB exactly, no static shared) ----
#define SM_U    0        // 4 warps x 8KB stripe: U fp16 4KB (union zbuf 32x64 f32 = 8KB)
#define SM_WHI  32768    // W2 fp16 hi [k][n] swizzled, 8KB
#define SM_WLO  40960    // W2 fp16 lo, 8KB
#define SMEM_DYN 49152

// ---------------- scratch ----------------
__device__ float g_h[N_NODES * HID];
__device__ float g_A[N_NODES * HID];
__device__ float g_Q[N_NODES * HID];
__device__ unsigned g_z[N_NODES * HID];     // ordered-encoded max accumulator
__device__ int   g_counts[N_NODES];
__device__ int   g_offsets[N_NODES + 1];
__device__ int   g_cursor[N_NODES];
__device__ int   g_csr[N_EDGES];
__device__ int   g_csr_dst[N_EDGES];
__device__ int   g_bsum[128];
__device__ int   g_bbase[128];
__device__ int   g_is64;
__device__ unsigned g_W2t_hi[N_LAYERS * 64 * 32];   // [L][k][n2] fp16x2
__device__ unsigned g_W2t_lo[N_LAYERS * 64 * 32];

// ---------------- helpers ----------------
__device__ __forceinline__ unsigned long long pk2(float x, float y) {
    unsigned long long r;
    asm("mov.b64 %0, {%1, %2};" : "=l"(r) : "f"(x), "f"(y));
    return r;
}
__device__ __forceinline__ unsigned long long pkdup(float x) {
    unsigned long long r;
    asm("mov.b64 %0, {%1, %1};" : "=l"(r) : "f"(x));
    return r;
}
__device__ __forceinline__ float2 upk2(unsigned long long v) {
    float2 r;
    asm("mov.b64 {%0, %1}, %2;" : "=f"(r.x), "=f"(r.y) : "l"(v));
    return r;
}
__device__ __forceinline__ unsigned long long ffma2(unsigned long long a,
                                                    unsigned long long b,
                                                    unsigned long long c) {
    unsigned long long d;
    asm("fma.rn.f32x2 %0, %1, %2, %3;" : "=l"(d) : "l"(a), "l"(b), "l"(c));
    return d;
}
__device__ __forceinline__ uint32_t smem_u32(const void* p) {
    uint32_t a;
    asm("{ .reg .u64 t; cvta.to.shared.u64 t, %1; cvt.u32.u64 %0, t; }" : "=r"(a) : "l"(p));
    return a;
}
__device__ __forceinline__ unsigned encf(float f) {
    unsigned u = __float_as_uint(f);
    return (u & 0x80000000u) ? ~u : (u | 0x80000000u);
}
__device__ __forceinline__ float decf(unsigned u) {
    return (u & 0x80000000u) ? __uint_as_float(u & 0x7FFFFFFFu) : __uint_as_float(~u);
}

// ---- warp-MMA primitives (base-target legal: sm_80+) ----
__device__ __forceinline__ void ldsm4(uint32_t* r, uint32_t a) {
    asm volatile("ldmatrix.sync.aligned.m8n8.x4.shared.b16 {%0,%1,%2,%3}, [%4];"
        : "=r"(r[0]), "=r"(r[1]), "=r"(r[2]), "=r"(r[3]) : "r"(a));
}
__device__ __forceinline__ void ldsm4t(uint32_t* r, uint32_t a) {
    asm volatile("ldmatrix.sync.aligned.m8n8.x4.trans.shared.b16 {%0,%1,%2,%3}, [%4];"
        : "=r"(r[0]), "=r"(r[1]), "=r"(r[2]), "=r"(r[3]) : "r"(a));
}
__device__ __forceinline__ void mma16816h(float* d, const uint32_t* a, uint32_t b0, uint32_t b1) {
    asm volatile("mma.sync.aligned.m16n8k16.row.col.f32.f16.f16.f32 "
        "{%0,%1,%2,%3}, {%4,%5,%6,%7}, {%8,%9}, {%0,%1,%2,%3};"
        : "+f"(d[0]), "+f"(d[1]), "+f"(d[2]), "+f"(d[3])
        : "r"(a[0]), "r"(a[1]), "r"(a[2]), "r"(a[3]), "r"(b0), "r"(b1));
}

// ---------------- CSR build ----------------
__global__ void k_zero(const int* __restrict__ ei32) {
    int i = blockIdx.x * blockDim.x + threadIdx.x;
    if (i < N_NODES) g_counts[i] = 0;
    if (blockIdx.x == 0 && threadIdx.x == 0) {
        int z = 0;
#pragma unroll
        for (int j = 1; j < 16; j += 2) z |= ei32[j];
        g_is64 = (z == 0) ? 1 : 0;
    }
}
__device__ __forceinline__ int edge_val(const int* __restrict__ e, int i, int is64) {
    return is64 ? e[2 * i] : e[i];
}
__global__ void k_hist(const int* __restrict__ ei32) {
    int e = blockIdx.x * blockDim.x + threadIdx.x;
    if (e < N_EDGES) {
        int d = edge_val(ei32, N_EDGES + e, g_is64);
        if ((unsigned)d < (unsigned)N_NODES) atomicAdd(&g_counts[d], 1);
    }
}
__device__ __forceinline__ int warp_incl_scan(int v, int lane) {
#pragma unroll
    for (int o = 1; o < 32; o <<= 1) {
        int t = __shfl_up_sync(0xffffffffu, v, o);
        if (lane >= o) v += t;
    }
    return v;
}
__global__ void __launch_bounds__(SCB) k_scan1() {
    __shared__ int ws[SCB / 32];
    int tid = threadIdx.x, lane = tid & 31, wid = tid >> 5;
    int i = blockIdx.x * SCB + tid;
    int v = (i < N_NODES) ? g_counts[i] : 0;
#pragma unroll
    for (int o = 16; o; o >>= 1) v += __shfl_xor_sync(0xffffffffu, v, o);
    if (lane == 0) ws[wid] = v;
    __syncthreads();
    if (wid == 0) {
        int s = (lane < SCB / 32) ? ws[lane] : 0;
#pragma unroll
        for (int o = 16; o; o >>= 1) s += __shfl_xor_sync(0xffffffffu, s, o);
        if (lane == 0) g_bsum[blockIdx.x] = s;
    }
}
__global__ void __launch_bounds__(128) k_scan2() {
    __shared__ int wsum[4];
    int tid = threadIdx.x, lane = tid & 31, wid = tid >> 5;
    int c = (tid < NSB) ? g_bsum[tid] : 0;
    int v = warp_incl_scan(c, lane);
    if (lane == 31) wsum[wid] = v;
    __syncthreads();
    int base = 0;
    for (int j = 0; j < wid; j++) base += wsum[j];
    v += base;
    if (tid < NSB) g_bbase[tid] = v - c;
    if (tid == NSB - 1) g_offsets[N_NODES] = v;
}
__global__ void __launch_bounds__(SCB) k_scan3() {
    __shared__ int wsum[SCB / 32];
    int tid = threadIdx.x, lane = tid & 31, wid = tid >> 5;
    int i = blockIdx.x * SCB + tid;
    int c = (i < N_NODES) ? g_counts[i] : 0;
    int v = warp_incl_scan(c, lane);
    if (lane == 31) wsum[wid] = v;
    __syncthreads();
    int base = g_bbase[blockIdx.x];
    for (int j = 0; j < wid; j++) base += wsum[j];
    int excl = base + v - c;
    if (i < N_NODES) {
        g_offsets[i] = excl;
        g_cursor[i]  = excl;
    }
}
__global__ void k_scatter(const int* __restrict__ ei32) {
    int e = blockIdx.x * blockDim.x + threadIdx.x;
    if (e < N_EDGES) {
        int is64 = g_is64;
        int d = edge_val(ei32, N_EDGES + e, is64);
        int s = edge_val(ei32, e, is64);
        if ((unsigned)d < (unsigned)N_NODES && (unsigned)s < (unsigned)N_NODES) {
            int pos = atomicAdd(&g_cursor[d], 1);
            g_csr[pos] = s;
            g_csr_dst[pos] = d;
        }
    }
}

// ---------------- W2 fp16 hi/lo precompute: [L][k][n2] ----------------
__global__ void k_w2cvt(const float* __restrict__ W2) {
    int i = blockIdx.x * blockDim.x + threadIdx.x;
    if (i >= N_LAYERS * 64 * 32) return;
    int L = i / 2048, rem = i % 2048;
    int k = rem >> 5, n2 = rem & 31;
    const float* WL = W2 + L * HID * HID;
    float f0 = WL[k * HID + 2 * n2];
    float f1 = WL[k * HID + 2 * n2 + 1];
    __half2 hb = __floats2half2_rn(f0, f1);
    float h0 = __low2float(hb), h1 = __high2float(hb);
    __half2 lb = __floats2half2_rn(f0 - h0, f1 - h1);
    g_W2t_hi[i] = *reinterpret_cast<unsigned*>(&hb);
    g_W2t_lo[i] = *reinterpret_cast<unsigned*>(&lb);
}

__global__ void k_zinit() {
    int i = blockIdx.x * blockDim.x + threadIdx.x;
    if (i < N_NODES * HID) g_z[i] = 0u;
}

// ---------------- input projection ----------------
__global__ void __launch_bounds__(256) k_proj(const float* __restrict__ x,
                                              const float* __restrict__ Wp,
                                              const float* __restrict__ bp) {
    __shared__ unsigned long long Wsp[IN_DIM * 32];
    __shared__ float xs[32][IN_DIM];
    int tid = threadIdx.x;
    for (int i = tid; i < IN_DIM * 32; i += 256) {
        int k = i >> 5, lc = i & 31;
        Wsp[i] = pk2(Wp[k * HID + 2 * lc], Wp[k * HID + 2 * lc + 1]);
    }
    int w = tid >> 5, l = tid & 31;
    int m0 = w * 4;
#pragma unroll
    for (int sub = 0; sub < 4; sub++) {
        int n = blockIdx.x * 32 + m0 + sub;
        if (n < N_NODES)
            ((float4*)xs[m0 + sub])[l] = ((const float4*)(x + (long)n * IN_DIM))[l];
    }
    __syncthreads();
    unsigned long long bv = pk2(bp[2 * l], bp[2 * l + 1]);
    unsigned long long acc[4] = {bv, bv, bv, bv};
#pragma unroll 4
    for (int k = 0; k < IN_DIM; k++) {
        unsigned long long wv = Wsp[k * 32 + l];
#pragma unroll
        for (int sub = 0; sub < 4; sub++)
            acc[sub] = ffma2(pkdup(xs[m0 + sub][k]), wv, acc[sub]);
    }
#pragma unroll
    for (int sub = 0; sub < 4; sub++) {
        int n = blockIdx.x * 32 + m0 + sub;
        if (n < N_NODES)
            *(float2*)(g_h + (long)n * HID + 2 * l) = upk2(acc[sub]);
    }
}

// ---------------- node GEMMs (optionally fused with previous-layer finish) ----------
// do_fin: h_new = relu(dec(z)+b2prev)+h_old per node, reset z; then A/Q from h_new.
__global__ void __launch_bounds__(256) k_AQ(const float* __restrict__ W1,
                                            const float* __restrict__ b1,
                                            const float* __restrict__ b2prev,
                                            int do_fin) {
    __shared__ unsigned long long Wsa[HID * 32];
    __shared__ unsigned long long Wsb[HID * 32];
    __shared__ float hs[32][HID];
    int tid = threadIdx.x;
    for (int i = tid; i < HID * 32; i += 256) {
        int k = i >> 5, lc = i & 31;
        Wsa[i] = pk2(W1[k * HID + 2 * lc], W1[k * HID + 2 * lc + 1]);
        Wsb[i] = pk2(W1[(HID + k) * HID + 2 * lc], W1[(HID + k) * HID + 2 * lc + 1]);
    }
    int w = tid >> 5, l = tid & 31;
    int m0 = w * 4;
#pragma unroll
    for (int sub = 0; sub < 4; sub++) {
        int n = blockIdx.x * 32 + m0 + sub;
        if (n >= N_NODES) continue;
        float2 h2 = *(const float2*)(g_h + (long)n * HID + 2 * l);
        if (do_fin) {
            int deg = g_offsets[n + 1] - g_offsets[n];
            if (deg > 0) {
                unsigned e0 = g_z[(long)n * HID + 2 * l];
                unsigned e1 = g_z[(long)n * HID + 2 * l + 1];
                float2 b2v = *(const float2*)(b2prev + 2 * l);
                h2.x = fmaxf(decf(e0) + b2v.x, 0.f) + h2.x;
                h2.y = fmaxf(decf(e1) + b2v.y, 0.f) + h2.y;
                *(uint2*)(g_z + (long)n * HID + 2 * l) = make_uint2(0u, 0u);
            }
            *(float2*)(g_h + (long)n * HID + 2 * l) = h2;
        }
        ((float2*)hs[m0 + sub])[l] = h2;
    }
    __syncthreads();
    unsigned long long accA[4] = {0ull, 0ull, 0ull, 0ull};
    unsigned long long accQ[4] = {0ull, 0ull, 0ull, 0ull};
#pragma unroll 4
    for (int k = 0; k < HID; k++) {
        unsigned long long wa = Wsa[k * 32 + l];
        unsigned long long wb = Wsb[k * 32 + l];
#pragma unroll
        for (int sub = 0; sub < 4; sub++) {
            unsigned long long hk2 = pkdup(hs[m0 + sub][k]);
            accA[sub] = ffma2(hk2, wa, accA[sub]);
            accQ[sub] = ffma2(hk2, wb, accQ[sub]);
        }
    }
    float2 bv = *(const float2*)(b1 + 2 * l);
#pragma unroll
    for (int sub = 0; sub < 4; sub++) {
        int n = blockIdx.x * 32 + m0 + sub;
        if (n >= N_NODES) continue;
        float2 fA = upk2(accA[sub]);
        float2 fQ = upk2(accQ[sub]);
        float2 A;
        A.x = fA.x - fQ.x + bv.x;
        A.y = fA.y - fQ.y + bv.y;
        *(float2*)(g_A + (long)n * HID + 2 * l) = A;
        *(float2*)(g_Q + (long)n * HID + 2 * l) = fQ;
    }
}

// ---------------- HMMA edge phase ----------------
// Contiguous chunk of 32-edge tiles per warp. U = relu(A[dst]+Q[src]) in fp16,
// 2-term MMA (U*Whi + U*Wlo), segmented max; interior segments plain-stored,
// chunk-boundary segments via encoded atomicMax.
__device__ __forceinline__ void flushmax(int node, int l, float m0, float m1, bool boundary) {
    unsigned* p = g_z + (long)node * HID + 2 * l;
    unsigned e0 = encf(m0), e1 = encf(m1);
    if (boundary) {
        atomicMax(p, e0);
        atomicMax(p + 1, e1);
    } else {
        *(uint2*)p = make_uint2(e0, e1);
    }
}

__global__ void __launch_bounds__(128, 4) k_edgemma(int layer) {
    extern __shared__ char sm[];
    uint32_t smb = smem_u32(sm);
    int tid = threadIdx.x, w = tid >> 5, l = tid & 31;

    const unsigned* wh = g_W2t_hi + layer * 2048;
    const unsigned* wl = g_W2t_lo + layer * 2048;
    for (int i = tid; i < 2048; i += 128) {
        int k = i >> 5, n2 = i & 31;
        uint32_t off = (uint32_t)(k * 128 + ((n2 * 4) ^ ((k & 7) << 4)));
        *(unsigned*)(sm + SM_WHI + off) = wh[i];
        *(unsigned*)(sm + SM_WLO + off) = wl[i];
    }
    __syncthreads();

    char* uw = sm + SM_U + w * 8192;         // U fp16 4KB (zbuf 8KB union)
    uint32_t uw32 = smb + SM_U + w * 8192;
    float* zb = (float*)uw;

    int lrow = l & 7;
    int arow = ((l >> 3) & 1) * 8 + lrow;
    int kgrp = l >> 4;
    uint32_t a_base0 = uw32 + arow * 128;
    uint32_t w_hi_base = smb + SM_WHI + arow * 128;
    uint32_t w_lo_base = smb + SM_WLO + arow * 128;

    int wg = blockIdx.x * 4 + w;
    int c0 = (int)((long)NT_W * wg / TW_TOT);
    int c1 = (int)((long)NT_W * (wg + 1) / TW_TOT);
    if (c0 >= c1) return;

    int mysrc = g_csr[c0 * 32 + l];
    int mydst = g_csr_dst[c0 * 32 + l];

    float m0 = -INFINITY, m1 = -INFINITY;
    int prev = INT_MIN;
    bool at_start = true;
    int prev_dst_stage = -1;
    float2 a2 = make_float2(0.f, 0.f);

    for (int t = c0; t < c1; t++) {
        // ---- stage 32 edges (fp16) ----
        for (int rr = 0; rr < 32; rr++) {
            int src = __shfl_sync(0xffffffffu, mysrc, rr);
            int dst = __shfl_sync(0xffffffffu, mydst, rr);
            if (dst != prev_dst_stage) {
                a2 = *(const float2*)(g_A + (long)dst * HID + 2 * l);
                prev_dst_stage = dst;
            }
            float2 q2 = *(const float2*)(g_Q + (long)src * HID + 2 * l);
            float u0 = fmaxf(a2.x + q2.x, 0.f);
            float u1 = fmaxf(a2.y + q2.y, 0.f);
            __half2 hb = __floats2half2_rn(u0, u1);
            uint32_t off = (uint32_t)(rr * 128 + ((l * 4) ^ ((rr & 7) << 4)));
            *(unsigned*)(uw + off) = *reinterpret_cast<unsigned*>(&hb);
        }
        __syncwarp();

        // prefetch next tile's indices
        int nsrc = 0, ndst = 0;
        if (t + 1 < c1) {
            nsrc = g_csr[(t + 1) * 32 + l];
            ndst = g_csr_dst[(t + 1) * 32 + l];
        }

        // ---- MMA: 2 terms (Whi, Wlo) ----
        float d[2][8][4];
#pragma unroll
        for (int rb = 0; rb < 2; rb++)
#pragma unroll
            for (int nb = 0; nb < 8; nb++)
#pragma unroll
                for (int j = 0; j < 4; j++) d[rb][nb][j] = 0.f;

#pragma unroll
        for (int ks = 0; ks < 4; ks++) {
            uint32_t axor = (uint32_t)(((ks * 2 + kgrp) ^ lrow) << 4);
            uint32_t ah[2][4];
            ldsm4(ah[0], a_base0 + axor);
            ldsm4(ah[1], a_base0 + 2048 + axor);
#pragma unroll
            for (int np = 0; np < 4; np++) {
                uint32_t bxor = (uint32_t)(((np * 2 + kgrp) ^ lrow) << 4);
                uint32_t bh[4], bl[4];
                ldsm4t(bh, w_hi_base + ks * 2048 + bxor);
                ldsm4t(bl, w_lo_base + ks * 2048 + bxor);
#pragma unroll
                for (int rb = 0; rb < 2; rb++) {
                    mma16816h(d[rb][2 * np],     ah[rb], bh[0], bh[1]);
                    mma16816h(d[rb][2 * np + 1], ah[rb], bh[2], bh[3]);
                    mma16816h(d[rb][2 * np],     ah[rb], bl[0], bl[1]);
                    mma16816h(d[rb][2 * np + 1], ah[rb], bl[2], bl[3]);
                }
            }
        }
        __syncwarp();

        // ---- D -> zbuf (swizzled) ----
#pragma unroll
        for (int rb = 0; rb < 2; rb++) {
#pragma unroll
            for (int nb = 0; nb < 8; nb++) {
                int c0w = nb * 8 + (l & 3) * 2;
                int r0 = rb * 16 + (l >> 2);
                int r1 = r0 + 8;
                *(float2*)&zb[r0 * 64 + (c0w ^ ((r0 & 7) << 3))] =
                    make_float2(d[rb][nb][0], d[rb][nb][1]);
                *(float2*)&zb[r1 * 64 + (c0w ^ ((r1 & 7) << 3))] =
                    make_float2(d[rb][nb][2], d[rb][nb][3]);
            }
        }
        __syncwarp();

        // ---- segmented max; interior segments plain-store, boundaries atomic ----
        for (int rr = 0; rr < 32; rr++) {
            int dcur = __shfl_sync(0xffffffffu, mydst, rr);
            if (dcur != prev) {
                if (prev != INT_MIN) {
                    flushmax(prev, l, m0, m1, at_start);
                    at_start = false;
                }
                m0 = -INFINITY; m1 = -INFINITY;
                prev = dcur;
            }
            float2 zv = *(const float2*)&zb[rr * 64 + ((2 * l) ^ ((rr & 7) << 3))];
            m0 = fmaxf(m0, zv.x);
            m1 = fmaxf(m1, zv.y);
        }
        __syncwarp();
        mysrc = nsrc;
        mydst = ndst;
    }
    if (prev != INT_MIN) flushmax(prev, l, m0, m1, true);   // chunk-end: boundary
}

// ---------------- last-layer finish: out = (relu(max+b2)+h) @ Wo + bo ----------------
__global__ void __launch_bounds__(256) k_finlast(const float* __restrict__ b2,
                                                 const float* __restrict__ Wo,
                                                 const float* __restrict__ bo,
                                                 float* __restrict__ out) {
    int w = threadIdx.x >> 5, l = threadIdx.x & 31;
    int n = blockIdx.x * 8 + w;
    if (n >= N_NODES) return;
    int deg = g_offsets[n + 1] - g_offsets[n];
    float2 r = *(const float2*)(g_h + (long)n * HID + 2 * l);
    if (deg > 0) {
        unsigned e0 = g_z[(long)n * HID + 2 * l];
        unsigned e1 = g_z[(long)n * HID + 2 * l + 1];
        float2 b2v = *(const float2*)(b2 + 2 * l);
        r.x = fmaxf(decf(e0) + b2v.x, 0.f) + r.x;
        r.y = fmaxf(decf(e1) + b2v.y, 0.f) + r.y;
    }
    float2 wo = *(const float2*)(Wo + 2 * l);
    float s = fmaf(r.x, wo.x, r.y * wo.y);
#pragma unroll
    for (int o = 16; o; o >>= 1) s += __shfl_xor_sync(0xffffffffu, s, o);
    if (l == 0) out[n] = s + bo[0];
}

// ---------------- launch ----------------
extern "C" void kernel_launch(void* const* d_in, const int* in_sizes, int n_in,
                              void* d_out, int out_size) {
    const float* x  = (const float*)d_in[0];
    const int*   ei = (const int*)d_in[1];
    const float* Wp = (const float*)d_in[2];
    const float* bp = (const float*)d_in[3];
    const float* W1 = (const float*)d_in[4];
    const float* b1 = (const float*)d_in[5];
    const float* W2 = (const float*)d_in[6];
    const float* b2 = (const float*)d_in[7];
    const float* Wo = (const float*)d_in[8];
    const float* bo = (const float*)d_in[9];
    float* out = (float*)d_out;

    k_zero<<<(N_NODES + 255) / 256, 256>>>(ei);
    k_hist<<<(N_EDGES + 255) / 256, 256>>>(ei);
    k_scan1<<<NSB, SCB>>>();
    k_scan2<<<1, 128>>>();
    k_scan3<<<NSB, SCB>>>();
    k_scatter<<<(N_EDGES + 255) / 256, 256>>>(ei);

    k_w2cvt<<<(N_LAYERS * 64 * 32 + 255) / 256, 256>>>(W2);
    k_zinit<<<(N_NODES * HID + 1023) / 1024, 1024>>>();

    const int NB = (N_NODES + 31) / 32;
    k_proj<<<NB, 256>>>(x, Wp, bp);
    for (int L = 0; L < N_LAYERS; L++) {
        k_AQ<<<NB, 256>>>(W1 + (long)L * 2 * HID * HID, b1 + (long)L * HID,
                          (L > 0) ? (b2 + (long)(L - 1) * HID) : b2, L > 0);
        k_edgemma<<<EMMA_BLOCKS, 128, SMEM_DYN>>>(L);
    }
    k_finlast<<<(N_NODES + 7) / 8, 256>>>(b2 + (long)(N_LAYERS - 1) * HID, Wo, bo, out);
}